// round 9
// baseline (speedup 1.0000x reference)
#include <cuda_runtime.h>
#include <cstdint>

#define IMG_W   1024
#define IMG_H   1024
#define IMG_PIX (IMG_W * IMG_H)
#define N_IMG   32
#define TOTAL_F ((size_t)N_IMG * IMG_PIX)
#define SMOOTH  1e-5
#define FULLM   0xffffffffu
#define BANDS   8
#define BROWS   (IMG_H / BANDS)       // 128
#define STRIPS  10
#define NSTEPS  150                   // prologue 24 | steady 114 | epilogue 12
#define D_PRO   24
#define D_STE   138
#define ROWQ    (IMG_W / 4)

// Scratch (no cudaMalloc allowed)
__device__ float g_bufA[2 * N_IMG * IMG_PIX];
__device__ float g_bufB[2 * N_IMG * IMG_PIX];
__device__ float g_skel[2 * N_IMG * IMG_PIX];
__device__ double g_sums[4];

__device__ __forceinline__ float4 ld4(const float* p) { return *(const float4*)p; }
__device__ __forceinline__ void st4(float* p, float4 v) { *(float4*)p = v; }

__device__ __forceinline__ void skel_upd(float4& s, const float4& d) {
    s.x += fmaxf(fmaf(-s.x, d.x, d.x), 0.0f);
    s.y += fmaxf(fmaf(-s.y, d.y, d.y), 0.0f);
    s.z += fmaxf(fmaf(-s.z, d.z, d.z), 0.0f);
    s.w += fmaxf(fmaf(-s.w, d.w, d.w), 0.0f);
}

// One sweep step at row Y, ring slot U.
// GUARD=false (steady state): every range/boundary condition is provably inactive ->
// fully branch-free. Prologue/epilogue run GUARD=true with band templates.
template <int T, int U, bool INIT, bool WRITE_E, bool TOPB, bool BOTB, bool GUARD, bool FUSE>
__device__ __forceinline__ void do_step(
    int Y, float4 (&L)[T + 1][3], float4& nxt, float4& snxt, float4& onxt,
    const float4* __restrict__ in4, float4* __restrict__ eout4,
    float4* __restrict__ skel4, const float4* __restrict__ other4,
    float* __restrict__ ring, float& acc_p, float& acc_s,
    int lane, int gq, bool loadok, bool outok, bool ledge, bool redge,
    int b0, int b1)
{
    const float INF  = __int_as_float(0x7f800000);
    const float NINF = -INF;
    constexpr int u  = U;
    constexpr int h1 = (U + 2) % 3;
    constexpr int h2 = (U + 1) % 3;

    // Consume prefetched input row Y; prefetch row Y+1.
    L[0][u] = nxt;
    {
        const int yy = Y + 1;
        bool ok = loadok;
        if (GUARD && TOPB) ok = ok && (yy >= 0);
        if (GUARD && BOTB) ok = ok && (yy < IMG_H);
        float4 v = make_float4(INF, INF, INF, INF);
        if (ok) v = in4[yy * ROWQ + gq];
        nxt = v;
    }
    // Consume prefetched skel row (Y-2); prefetch row Y-1.
    float4 scur = snxt;
    if (!INIT) {
        const int yy = Y - 1;
        bool ok = outok;
        if (GUARD) ok = ok && (yy >= b0) && (yy < b1);
        float4 sv = make_float4(0.0f, 0.0f, 0.0f, 0.0f);
        if (ok) sv = skel4[yy * ROWQ + gq];
        snxt = sv;
    }
    // Consume prefetched other row (Y-T-1); prefetch row Y-T.
    float4 ocur = onxt;
    if (FUSE) {
        const int yy = Y - T;
        bool ok = outok;
        if (GUARD) ok = ok && (yy >= b0) && (yy < b1);
        float4 ov = make_float4(0.0f, 0.0f, 0.0f, 0.0f);
        if (ok) ov = other4[yy * ROWQ + gq];
        onxt = ov;
    }

    // Erosion levels: level j computes row r = Y - j from level j-1 rows r-1..r+1
#pragma unroll
    for (int j = 1; j <= T; ++j) {
        const int r = Y - j;
        const float4 up = L[j - 1][h2];
        const float4 ce = L[j - 1][h1];
        const float4 dn = L[j - 1][u];
        const float cl = __shfl_up_sync(FULLM, ce.w, 1);
        const float cr = __shfl_down_sync(FULLM, ce.x, 1);
        float4 o;
        o.x = fminf(fminf(fminf(up.x, dn.x), fminf(cl,   ce.y)), ce.x);
        o.y = fminf(fminf(fminf(up.y, dn.y), fminf(ce.x, ce.z)), ce.y);
        o.z = fminf(fminf(fminf(up.z, dn.z), fminf(ce.y, ce.w)), ce.z);
        o.w = fminf(fminf(fminf(up.w, dn.w), fminf(ce.z, cr  )), ce.w);
        if (GUARD && TOPB) { if (r < 0)      o = make_float4(INF, INF, INF, INF); }
        if (GUARD && BOTB) { if (r >= IMG_H) o = make_float4(INF, INF, INF, INF); }
        L[j][u] = o;
        if (WRITE_E && j == T) {
            bool ok = outok;
            if (GUARD) ok = ok && (r >= b0) && (r < b1);
            if (ok) eout4[r * ROWQ + gq] = o;
        }
    }

    // Deltas: delta_k at row y = Y - k - 2
#pragma unroll
    for (int k = 0; k < T; ++k) {
        const int y = Y - k - 2;
        if (GUARD) { if (y < b0 || y >= b1) continue; }

        float4 a = L[k + 1][h2];
        const float4 b = L[k + 1][h1];
        float4 c = L[k + 1][u];
        if (GUARD && TOPB) { if (y == 0)         a = make_float4(NINF, NINF, NINF, NINF); }
        if (GUARD && BOTB) { if (y == IMG_H - 1) c = make_float4(NINF, NINF, NINF, NINF); }

        float4 vm;
        vm.x = fmaxf(a.x, fmaxf(b.x, c.x));
        vm.y = fmaxf(a.y, fmaxf(b.y, c.y));
        vm.z = fmaxf(a.z, fmaxf(b.z, c.z));
        vm.w = fmaxf(a.w, fmaxf(b.w, c.w));
        float vl = __shfl_up_sync(FULLM, vm.w, 1);
        float vr = __shfl_down_sync(FULLM, vm.x, 1);
        if (ledge) vl = NINF;
        if (redge) vr = NINF;
        float4 op;
        op.x = fmaxf(vm.x, fmaxf(vl,   vm.y));
        op.y = fmaxf(vm.y, fmaxf(vm.x, vm.z));
        op.z = fmaxf(vm.z, fmaxf(vm.y, vm.w));
        op.w = fmaxf(vm.w, fmaxf(vm.z, vr));

        const float4 e = L[k][h2];
        float4 d;
        d.x = fmaxf(e.x - op.x, 0.0f);
        d.y = fmaxf(e.y - op.y, 0.0f);
        d.z = fmaxf(e.z - op.z, 0.0f);
        d.w = fmaxf(e.w - op.w, 0.0f);

        float* srow = ring + ((y & 15) << 7) + (lane << 2);
        float4 s;
        if (k == 0) {
            if (INIT) s = make_float4(0.0f, 0.0f, 0.0f, 0.0f);
            else      s = scur;
        } else {
            s = ld4(srow);
        }
        skel_upd(s, d);
        if (k == T - 1) {
            if (outok) {
                skel4[y * ROWQ + gq] = s;
                if (FUSE) {
                    acc_p += s.x * ocur.x + s.y * ocur.y + s.z * ocur.z + s.w * ocur.w;
                    acc_s += s.x + s.y + s.z + s.w;
                }
            }
        } else {
            st4(srow, s);
        }
    }
}

template <int T, bool INIT, bool WRITE_E, bool TOPB, bool BOTB, bool FUSE>
__device__ __forceinline__ void sweep(
    const float4* __restrict__ in4, float4* __restrict__ eout4,
    float4* __restrict__ skel4, const float4* __restrict__ other4,
    float* __restrict__ ring, double* __restrict__ sums, int t_idx,
    int lane, int gq, bool loadok, bool outok, bool ledge, bool redge,
    int b0, int b1)
{
    float4 L[T + 1][3];
    const float INF = __int_as_float(0x7f800000);
#pragma unroll
    for (int j = 0; j <= T; ++j)
#pragma unroll
        for (int s = 0; s < 3; ++s)
            L[j][s] = make_float4(INF, INF, INF, INF);

    const int Ys = b0 - 12;

    float4 nxt = make_float4(INF, INF, INF, INF);
    {
        bool ok = loadok;
        if (TOPB) ok = ok && (Ys >= 0);
        if (ok) nxt = in4[Ys * ROWQ + gq];
    }
    float4 snxt = make_float4(0.0f, 0.0f, 0.0f, 0.0f);
    float4 onxt = make_float4(0.0f, 0.0f, 0.0f, 0.0f);
    float acc_p = 0.0f, acc_s = 0.0f;

#define STEP3(DD, GU, TB, BB)                                                              \
    do {                                                                                   \
        do_step<T, 0, INIT, WRITE_E, TB, BB, GU, FUSE>(Ys + (DD),     L, nxt, snxt, onxt,  \
            in4, eout4, skel4, other4, ring, acc_p, acc_s,                                 \
            lane, gq, loadok, outok, ledge, redge, b0, b1);                                \
        do_step<T, 1, INIT, WRITE_E, TB, BB, GU, FUSE>(Ys + (DD) + 1, L, nxt, snxt, onxt,  \
            in4, eout4, skel4, other4, ring, acc_p, acc_s,                                 \
            lane, gq, loadok, outok, ledge, redge, b0, b1);                                \
        do_step<T, 2, INIT, WRITE_E, TB, BB, GU, FUSE>(Ys + (DD) + 2, L, nxt, snxt, onxt,  \
            in4, eout4, skel4, other4, ring, acc_p, acc_s,                                 \
            lane, gq, loadok, outok, ledge, redge, b0, b1);                                \
    } while (0)

    // Prologue (guards on, band specialization)
    for (int d = 0; d < D_PRO; d += 3) STEP3(d, true, TOPB, BOTB);
    // Steady state: all guards provably inactive -> branch-free
    for (int d = D_PRO; d < D_STE; d += 3) STEP3(d, false, false, false);
    // Epilogue (guards on)
    for (int d = D_STE; d < NSTEPS; d += 3) STEP3(d, true, TOPB, BOTB);
#undef STEP3

    if (FUSE) {
#pragma unroll
        for (int off = 16; off > 0; off >>= 1) {
            acc_p += __shfl_down_sync(FULLM, acc_p, off);
            acc_s += __shfl_down_sync(FULLM, acc_s, off);
        }
        if (lane == 0) {
            atomicAdd(&sums[2 * t_idx],     (double)acc_p);
            atomicAdd(&sums[2 * t_idx + 1], (double)acc_s);
        }
    }
}

// Warp-autonomous erosion tower: no block barriers.
template <int T, bool INIT, bool WRITE_E, bool FUSE>
__global__ __launch_bounds__(128, 3)
void tower(const float* __restrict__ p0, const float* __restrict__ p1,
           const float* __restrict__ o0, const float* __restrict__ o1,
           float* __restrict__ eout, float* __restrict__ gskel)
{
    __shared__ float ring[4][16 * 128];

    const int wid  = threadIdx.x >> 5;
    const int lane = threadIdx.x & 31;
    const int w    = blockIdx.x * 4 + wid;
    const int n    = w / (BANDS * STRIPS);
    const int rem  = w % (BANDS * STRIPS);
    const int band = rem / STRIPS;
    const int strip = rem % STRIPS;
    const int b0 = band * BROWS, b1 = b0 + BROWS;

    const int gq = 26 * strip - 3 + lane;
    const bool loadok = (gq >= 0) && (gq < ROWQ);
    const bool outok  = (lane >= 3) && (lane < 29) && (gq < ROWQ);
    const bool ledge  = (gq == 0);
    const bool redge  = (gq == ROWQ - 1);

    const float* src;
    if (INIT) src = (n < N_IMG) ? (p0 + (size_t)n * IMG_PIX)
                                : (p1 + (size_t)(n - N_IMG) * IMG_PIX);
    else      src = p0 + (size_t)n * IMG_PIX;
    const float* oth = nullptr;
    const int t_idx = (n >= N_IMG) ? 1 : 0;
    if (FUSE) oth = (n < N_IMG) ? (o0 + (size_t)n * IMG_PIX)
                                : (o1 + (size_t)(n - N_IMG) * IMG_PIX);

    const float4* in4   = (const float4*)src;
    float4*       eout4 = (float4*)(WRITE_E ? (eout + (size_t)n * IMG_PIX) : nullptr);
    float4*       skel4 = (float4*)(gskel + (size_t)n * IMG_PIX);
    const float4* oth4  = (const float4*)oth;
    float* myring = &ring[wid][0];

    if (band == 0)
        sweep<T, INIT, WRITE_E, true,  false, FUSE>(in4, eout4, skel4, oth4, myring, g_sums,
            t_idx, lane, gq, loadok, outok, ledge, redge, b0, b1);
    else if (band == BANDS - 1)
        sweep<T, INIT, WRITE_E, false, true,  FUSE>(in4, eout4, skel4, oth4, myring, g_sums,
            t_idx, lane, gq, loadok, outok, ledge, redge, b0, b1);
    else
        sweep<T, INIT, WRITE_E, false, false, FUSE>(in4, eout4, skel4, oth4, myring, g_sums,
            t_idx, lane, gq, loadok, outok, ledge, redge, b0, b1);
}

__global__ void zero_sums(double* sums) {
    if (threadIdx.x < 4) sums[threadIdx.x] = 0.0;
}

__global__ void finalize_cldice(const double* __restrict__ sums, float* __restrict__ out) {
    const double tprec = (sums[0] + SMOOTH) / (sums[1] + SMOOTH);
    const double tsens = (sums[2] + SMOOTH) / (sums[3] + SMOOTH);
    out[0] = (float)(1.0 - 2.0 * (tprec * tsens) / (tprec + tsens));
}

extern "C" void kernel_launch(void* const* d_in, const int* in_sizes, int n_in,
                              void* d_out, int out_size) {
    const float* target = (const float*)d_in[0];
    const float* inputs = (const float*)d_in[1];
    float* out = (float*)d_out;

    static float* bufA = nullptr;
    static float* bufB = nullptr;
    static float* skel = nullptr;
    static double* sums = nullptr;
    if (!bufA) {
        cudaGetSymbolAddress((void**)&bufA, g_bufA);
        cudaGetSymbolAddress((void**)&bufB, g_bufB);
        cudaGetSymbolAddress((void**)&skel, g_skel);
        cudaGetSymbolAddress((void**)&sums, g_sums);
    }

    // warps: 64 images x 8 bands x 10 strips = 5120 -> 1280 blocks x 4 warps
    const int NBLK = (2 * N_IMG * BANDS * STRIPS) / 4;
    const dim3 block(128);

    zero_sums<<<1, 32>>>(sums);

    // Erosion tower E_0..E_26, deltas 0..25: passes T = 9, 9, 8.
    // Pass 3 fuses the skel/other reduction.
    tower<9, true,  true,  false><<<NBLK, block>>>(inputs, target, nullptr, nullptr, bufA, skel);
    tower<9, false, true,  false><<<NBLK, block>>>(bufA, nullptr, nullptr, nullptr, bufB, skel);
    tower<8, false, false, true ><<<NBLK, block>>>(bufB, nullptr, target, inputs, nullptr, skel);

    finalize_cldice<<<1, 1>>>(sums, out);
}

// round 10
// speedup vs baseline: 1.1232x; 1.1232x over previous
#include <cuda_runtime.h>
#include <cstdint>

#define IMG_W   1024
#define IMG_H   1024
#define IMG_PIX (IMG_W * IMG_H)
#define N_IMG   32
#define TOTAL_F ((size_t)N_IMG * IMG_PIX)
#define SMOOTH  1e-5
#define FULLM   0xffffffffu
#define BANDS   8
#define BROWS   (IMG_H / BANDS)       // 128
#define STRIPS  10
#define NSTEPS  150                   // >= BROWS + 22, multiple of 3
#define ROWQ    (IMG_W / 4)

// Scratch (no cudaMalloc allowed)
__device__ float g_bufA[2 * N_IMG * IMG_PIX];
__device__ float g_bufB[2 * N_IMG * IMG_PIX];
__device__ float g_skel[2 * N_IMG * IMG_PIX];
__device__ double g_sums[4];

__device__ __forceinline__ float4 ld4(const float* p) { return *(const float4*)p; }
__device__ __forceinline__ void st4(float* p, float4 v) { *(float4*)p = v; }

__device__ __forceinline__ void skel_upd(float4& s, const float4& d) {
    s.x += fmaxf(fmaf(-s.x, d.x, d.x), 0.0f);
    s.y += fmaxf(fmaf(-s.y, d.y, d.y), 0.0f);
    s.z += fmaxf(fmaf(-s.z, d.z, d.z), 0.0f);
    s.w += fmaxf(fmaf(-s.w, d.w, d.w), 0.0f);
}

// One sweep step at row Y, ring slot U (compile-time).
// Ring invariant after step Y: L[j][U] = level-j row (Y-j); (U+2)%3 = that row-1; (U+1)%3 = row-2.
// nxt  = input row Y (prefetched); refilled with row Y+1.
// snxt = skel row Y-2 (prefetched); refilled with row Y-1.
// onxt (FUSE) = other row Y-T-1 (prefetched); refilled with row Y-T.
template <int T, int U, bool INIT, bool WRITE_E, bool TOPB, bool BOTB, bool FUSE>
__device__ __forceinline__ void do_step(
    int Y, float4 (&L)[T + 1][3], float4& nxt, float4& snxt, float4& onxt,
    const float4* __restrict__ in4, float4* __restrict__ eout4,
    float4* __restrict__ skel4, const float4* __restrict__ other4,
    float* __restrict__ ring, float& acc_p, float& acc_s,
    int lane, int gq, bool loadok, bool outok, bool ledge, bool redge,
    int b0, int b1)
{
    const float INF  = __int_as_float(0x7f800000);
    const float NINF = -INF;
    constexpr int u  = U;
    constexpr int h1 = (U + 2) % 3;
    constexpr int h2 = (U + 1) % 3;

    // Consume prefetched input row Y; prefetch row Y+1.
    L[0][u] = nxt;
    {
        const int yy = Y + 1;
        bool ok = loadok;
        if (TOPB) ok = ok && (yy >= 0);
        if (BOTB) ok = ok && (yy < IMG_H);
        float4 v = make_float4(INF, INF, INF, INF);
        if (ok) v = in4[yy * ROWQ + gq];
        nxt = v;
    }
    // Consume prefetched skel row (Y-2); prefetch row Y-1.
    float4 scur = snxt;
    if (!INIT) {
        const int yy = Y - 1;
        float4 sv = make_float4(0.0f, 0.0f, 0.0f, 0.0f);
        if (yy >= b0 && yy < b1 && outok) sv = skel4[yy * ROWQ + gq];
        snxt = sv;
    }
    // Consume prefetched other row (Y-T-1); prefetch row Y-T.
    float4 ocur = onxt;
    if (FUSE) {
        const int yy = Y - T;
        float4 ov = make_float4(0.0f, 0.0f, 0.0f, 0.0f);
        if (yy >= b0 && yy < b1 && outok) ov = other4[yy * ROWQ + gq];
        onxt = ov;
    }

    // Erosion levels: level j computes row r = Y - j from level j-1 rows r-1..r+1
#pragma unroll
    for (int j = 1; j <= T; ++j) {
        const int r = Y - j;
        const float4 up = L[j - 1][h2];
        const float4 ce = L[j - 1][h1];
        const float4 dn = L[j - 1][u];
        const float cl = __shfl_up_sync(FULLM, ce.w, 1);
        const float cr = __shfl_down_sync(FULLM, ce.x, 1);
        float4 o;
        o.x = fminf(fminf(fminf(up.x, dn.x), fminf(cl,   ce.y)), ce.x);
        o.y = fminf(fminf(fminf(up.y, dn.y), fminf(ce.x, ce.z)), ce.y);
        o.z = fminf(fminf(fminf(up.z, dn.z), fminf(ce.y, ce.w)), ce.z);
        o.w = fminf(fminf(fminf(up.w, dn.w), fminf(ce.z, cr  )), ce.w);
        if (TOPB) { if (r < 0)      o = make_float4(INF, INF, INF, INF); }
        if (BOTB) { if (r >= IMG_H) o = make_float4(INF, INF, INF, INF); }
        L[j][u] = o;
        if (WRITE_E && j == T) {
            if (r >= b0 && r < b1 && outok) eout4[r * ROWQ + gq] = o;
        }
    }

    // Deltas: delta_k at row y = Y - k - 2
#pragma unroll
    for (int k = 0; k < T; ++k) {
        const int y = Y - k - 2;
        if (y < b0 || y >= b1) continue;

        float4 a = L[k + 1][h2];
        const float4 b = L[k + 1][h1];
        float4 c = L[k + 1][u];
        if (TOPB) { if (y == 0)         a = make_float4(NINF, NINF, NINF, NINF); }
        if (BOTB) { if (y == IMG_H - 1) c = make_float4(NINF, NINF, NINF, NINF); }

        float4 vm;
        vm.x = fmaxf(a.x, fmaxf(b.x, c.x));
        vm.y = fmaxf(a.y, fmaxf(b.y, c.y));
        vm.z = fmaxf(a.z, fmaxf(b.z, c.z));
        vm.w = fmaxf(a.w, fmaxf(b.w, c.w));
        float vl = __shfl_up_sync(FULLM, vm.w, 1);
        float vr = __shfl_down_sync(FULLM, vm.x, 1);
        if (ledge) vl = NINF;
        if (redge) vr = NINF;
        float4 op;
        op.x = fmaxf(vm.x, fmaxf(vl,   vm.y));
        op.y = fmaxf(vm.y, fmaxf(vm.x, vm.z));
        op.z = fmaxf(vm.z, fmaxf(vm.y, vm.w));
        op.w = fmaxf(vm.w, fmaxf(vm.z, vr));

        const float4 e = L[k][h2];
        float4 d;
        d.x = fmaxf(e.x - op.x, 0.0f);
        d.y = fmaxf(e.y - op.y, 0.0f);
        d.z = fmaxf(e.z - op.z, 0.0f);
        d.w = fmaxf(e.w - op.w, 0.0f);

        float* srow = ring + ((y & 15) << 7) + (lane << 2);
        float4 s;
        if (k == 0) {
            if (INIT) s = make_float4(0.0f, 0.0f, 0.0f, 0.0f);
            else      s = scur;
        } else {
            s = ld4(srow);
        }
        skel_upd(s, d);
        if (k == T - 1) {
            if (outok) {
                skel4[y * ROWQ + gq] = s;
                if (FUSE) {
                    acc_p += s.x * ocur.x + s.y * ocur.y + s.z * ocur.z + s.w * ocur.w;
                    acc_s += s.x + s.y + s.z + s.w;
                }
            }
        } else {
            st4(srow, s);
        }
    }
}

template <int T, bool INIT, bool WRITE_E, bool TOPB, bool BOTB, bool FUSE>
__device__ __forceinline__ void sweep(
    const float4* __restrict__ in4, float4* __restrict__ eout4,
    float4* __restrict__ skel4, const float4* __restrict__ other4,
    float* __restrict__ ring, double* __restrict__ sums, int t_idx,
    int lane, int gq, bool loadok, bool outok, bool ledge, bool redge,
    int b0, int b1)
{
    float4 L[T + 1][3];
    const float INF = __int_as_float(0x7f800000);
#pragma unroll
    for (int j = 0; j <= T; ++j)
#pragma unroll
        for (int s = 0; s < 3; ++s)
            L[j][s] = make_float4(INF, INF, INF, INF);

    const int Ys = b0 - 12;

    float4 nxt = make_float4(INF, INF, INF, INF);
    {
        bool ok = loadok;
        if (TOPB) ok = ok && (Ys >= 0);
        if (ok) nxt = in4[Ys * ROWQ + gq];
    }
    float4 snxt = make_float4(0.0f, 0.0f, 0.0f, 0.0f);
    float4 onxt = make_float4(0.0f, 0.0f, 0.0f, 0.0f);
    float acc_p = 0.0f, acc_s = 0.0f;

    for (int d = 0; d < NSTEPS; d += 3) {
        do_step<T, 0, INIT, WRITE_E, TOPB, BOTB, FUSE>(Ys + d,     L, nxt, snxt, onxt,
            in4, eout4, skel4, other4, ring, acc_p, acc_s,
            lane, gq, loadok, outok, ledge, redge, b0, b1);
        do_step<T, 1, INIT, WRITE_E, TOPB, BOTB, FUSE>(Ys + d + 1, L, nxt, snxt, onxt,
            in4, eout4, skel4, other4, ring, acc_p, acc_s,
            lane, gq, loadok, outok, ledge, redge, b0, b1);
        do_step<T, 2, INIT, WRITE_E, TOPB, BOTB, FUSE>(Ys + d + 2, L, nxt, snxt, onxt,
            in4, eout4, skel4, other4, ring, acc_p, acc_s,
            lane, gq, loadok, outok, ledge, redge, b0, b1);
    }

    if (FUSE) {
#pragma unroll
        for (int off = 16; off > 0; off >>= 1) {
            acc_p += __shfl_down_sync(FULLM, acc_p, off);
            acc_s += __shfl_down_sync(FULLM, acc_s, off);
        }
        if (lane == 0) {
            atomicAdd(&sums[2 * t_idx],     (double)acc_p);
            atomicAdd(&sums[2 * t_idx + 1], (double)acc_s);
        }
    }
}

// Warp-autonomous erosion tower: no block barriers.
template <int T, bool INIT, bool WRITE_E, bool FUSE>
__global__ __launch_bounds__(128, 3)
void tower(const float* __restrict__ p0, const float* __restrict__ p1,
           const float* __restrict__ o0, const float* __restrict__ o1,
           float* __restrict__ eout, float* __restrict__ gskel)
{
    __shared__ float ring[4][16 * 128];

    const int wid  = threadIdx.x >> 5;
    const int lane = threadIdx.x & 31;
    const int w    = blockIdx.x * 4 + wid;
    const int n    = w / (BANDS * STRIPS);
    const int rem  = w % (BANDS * STRIPS);
    const int band = rem / STRIPS;
    const int strip = rem % STRIPS;
    const int b0 = band * BROWS, b1 = b0 + BROWS;

    const int gq = 26 * strip - 3 + lane;
    const bool loadok = (gq >= 0) && (gq < ROWQ);
    const bool outok  = (lane >= 3) && (lane < 29) && (gq < ROWQ);
    const bool ledge  = (gq == 0);
    const bool redge  = (gq == ROWQ - 1);

    const float* src;
    if (INIT) src = (n < N_IMG) ? (p0 + (size_t)n * IMG_PIX)
                                : (p1 + (size_t)(n - N_IMG) * IMG_PIX);
    else      src = p0 + (size_t)n * IMG_PIX;
    const float* oth = nullptr;
    const int t_idx = (n >= N_IMG) ? 1 : 0;
    if (FUSE) oth = (n < N_IMG) ? (o0 + (size_t)n * IMG_PIX)
                                : (o1 + (size_t)(n - N_IMG) * IMG_PIX);

    const float4* in4   = (const float4*)src;
    float4*       eout4 = (float4*)(WRITE_E ? (eout + (size_t)n * IMG_PIX) : nullptr);
    float4*       skel4 = (float4*)(gskel + (size_t)n * IMG_PIX);
    const float4* oth4  = (const float4*)oth;
    float* myring = &ring[wid][0];

    if (band == 0)
        sweep<T, INIT, WRITE_E, true,  false, FUSE>(in4, eout4, skel4, oth4, myring, g_sums,
            t_idx, lane, gq, loadok, outok, ledge, redge, b0, b1);
    else if (band == BANDS - 1)
        sweep<T, INIT, WRITE_E, false, true,  FUSE>(in4, eout4, skel4, oth4, myring, g_sums,
            t_idx, lane, gq, loadok, outok, ledge, redge, b0, b1);
    else
        sweep<T, INIT, WRITE_E, false, false, FUSE>(in4, eout4, skel4, oth4, myring, g_sums,
            t_idx, lane, gq, loadok, outok, ledge, redge, b0, b1);
}

__global__ void zero_sums(double* sums) {
    if (threadIdx.x < 4) sums[threadIdx.x] = 0.0;
}

__global__ void finalize_cldice(const double* __restrict__ sums, float* __restrict__ out) {
    const double tprec = (sums[0] + SMOOTH) / (sums[1] + SMOOTH);
    const double tsens = (sums[2] + SMOOTH) / (sums[3] + SMOOTH);
    out[0] = (float)(1.0 - 2.0 * (tprec * tsens) / (tprec + tsens));
}

extern "C" void kernel_launch(void* const* d_in, const int* in_sizes, int n_in,
                              void* d_out, int out_size) {
    const float* target = (const float*)d_in[0];
    const float* inputs = (const float*)d_in[1];
    float* out = (float*)d_out;

    static float* bufA = nullptr;
    static float* bufB = nullptr;
    static float* skel = nullptr;
    static double* sums = nullptr;
    if (!bufA) {
        cudaGetSymbolAddress((void**)&bufA, g_bufA);
        cudaGetSymbolAddress((void**)&bufB, g_bufB);
        cudaGetSymbolAddress((void**)&skel, g_skel);
        cudaGetSymbolAddress((void**)&sums, g_sums);
    }

    // warps: 64 images x 8 bands x 10 strips = 5120 -> 1280 blocks x 4 warps
    const int NBLK = (2 * N_IMG * BANDS * STRIPS) / 4;
    const dim3 block(128);

    zero_sums<<<1, 32>>>(sums);

    // Erosion tower E_0..E_26, deltas 0..25: passes T = 9, 9, 8.
    // Pass 3 fuses the skel/other reduction (no separate reduce pass).
    tower<9, true,  true,  false><<<NBLK, block>>>(inputs, target, nullptr, nullptr, bufA, skel);
    tower<9, false, true,  false><<<NBLK, block>>>(bufA, nullptr, nullptr, nullptr, bufB, skel);
    tower<8, false, false, true ><<<NBLK, block>>>(bufB, nullptr, target, inputs, nullptr, skel);

    finalize_cldice<<<1, 1>>>(sums, out);
}

// round 11
// speedup vs baseline: 1.4376x; 1.2799x over previous
#include <cuda_runtime.h>
#include <cstdint>

#define IMG_W   1024
#define IMG_H   1024
#define IMG_PIX (IMG_W * IMG_H)
#define N_IMG   32
#define TOTAL_F ((size_t)N_IMG * IMG_PIX)
#define SMOOTH  1e-5
#define FULLM   0xffffffffu
#define NBANDS  11                    // bands 0..9: 93 rows; band 10: 94 rows
#define BROW0   93
#define STRIPS  10
#define ROWQ    (IMG_W / 4)

// Scratch (no cudaMalloc allowed)
__device__ float g_bufA[2 * N_IMG * IMG_PIX];
__device__ float g_bufB[2 * N_IMG * IMG_PIX];
__device__ float g_skel[2 * N_IMG * IMG_PIX];
__device__ double g_sums[4];

__device__ __forceinline__ float4 ld4(const float* p) { return *(const float4*)p; }
__device__ __forceinline__ void st4(float* p, float4 v) { *(float4*)p = v; }

__device__ __forceinline__ void skel_upd(float4& s, const float4& d) {
    s.x += fmaxf(fmaf(-s.x, d.x, d.x), 0.0f);
    s.y += fmaxf(fmaf(-s.y, d.y, d.y), 0.0f);
    s.z += fmaxf(fmaf(-s.z, d.z, d.z), 0.0f);
    s.w += fmaxf(fmaf(-s.w, d.w, d.w), 0.0f);
}

// One sweep step at row Y, ring slot U (compile-time).
// Ring invariant after step Y: L[j][U] = level-j row (Y-j); (U+2)%3 = that row-1; (U+1)%3 = row-2.
template <int T, int U, bool INIT, bool WRITE_E, bool TOPB, bool BOTB, bool FUSE>
__device__ __forceinline__ void do_step(
    int Y, float4 (&L)[T + 1][3], float4& nxt, float4& snxt, float4& onxt,
    const float4* __restrict__ in4, float4* __restrict__ eout4,
    float4* __restrict__ skel4, const float4* __restrict__ other4,
    float* __restrict__ ring, float& acc_p, float& acc_s,
    int lane, int gq, bool loadok, bool outok, bool ledge, bool redge,
    int b0, int b1)
{
    const float INF  = __int_as_float(0x7f800000);
    const float NINF = -INF;
    constexpr int u  = U;
    constexpr int h1 = (U + 2) % 3;
    constexpr int h2 = (U + 1) % 3;

    // Consume prefetched input row Y; prefetch row Y+1.
    L[0][u] = nxt;
    {
        const int yy = Y + 1;
        bool ok = loadok;
        if (TOPB) ok = ok && (yy >= 0);
        if (BOTB) ok = ok && (yy < IMG_H);
        float4 v = make_float4(INF, INF, INF, INF);
        if (ok) v = in4[yy * ROWQ + gq];
        nxt = v;
    }
    // Consume prefetched skel row (Y-2); prefetch row Y-1.
    float4 scur = snxt;
    if (!INIT) {
        const int yy = Y - 1;
        float4 sv = make_float4(0.0f, 0.0f, 0.0f, 0.0f);
        if (yy >= b0 && yy < b1 && outok) sv = skel4[yy * ROWQ + gq];
        snxt = sv;
    }
    // Consume prefetched other row (Y-T-1); prefetch row Y-T.
    float4 ocur = onxt;
    if (FUSE) {
        const int yy = Y - T;
        float4 ov = make_float4(0.0f, 0.0f, 0.0f, 0.0f);
        if (yy >= b0 && yy < b1 && outok) ov = other4[yy * ROWQ + gq];
        onxt = ov;
    }

    // Erosion levels: level j computes row r = Y - j from level j-1 rows r-1..r+1
#pragma unroll
    for (int j = 1; j <= T; ++j) {
        const int r = Y - j;
        const float4 up = L[j - 1][h2];
        const float4 ce = L[j - 1][h1];
        const float4 dn = L[j - 1][u];
        const float cl = __shfl_up_sync(FULLM, ce.w, 1);
        const float cr = __shfl_down_sync(FULLM, ce.x, 1);
        float4 o;
        o.x = fminf(fminf(fminf(up.x, dn.x), fminf(cl,   ce.y)), ce.x);
        o.y = fminf(fminf(fminf(up.y, dn.y), fminf(ce.x, ce.z)), ce.y);
        o.z = fminf(fminf(fminf(up.z, dn.z), fminf(ce.y, ce.w)), ce.z);
        o.w = fminf(fminf(fminf(up.w, dn.w), fminf(ce.z, cr  )), ce.w);
        if (TOPB) { if (r < 0)      o = make_float4(INF, INF, INF, INF); }
        if (BOTB) { if (r >= IMG_H) o = make_float4(INF, INF, INF, INF); }
        L[j][u] = o;
        if (WRITE_E && j == T) {
            if (r >= b0 && r < b1 && outok) eout4[r * ROWQ + gq] = o;
        }
    }

    // Deltas: delta_k at row y = Y - k - 2
#pragma unroll
    for (int k = 0; k < T; ++k) {
        const int y = Y - k - 2;
        if (y < b0 || y >= b1) continue;

        float4 a = L[k + 1][h2];
        const float4 b = L[k + 1][h1];
        float4 c = L[k + 1][u];
        if (TOPB) { if (y == 0)         a = make_float4(NINF, NINF, NINF, NINF); }
        if (BOTB) { if (y == IMG_H - 1) c = make_float4(NINF, NINF, NINF, NINF); }

        float4 vm;
        vm.x = fmaxf(a.x, fmaxf(b.x, c.x));
        vm.y = fmaxf(a.y, fmaxf(b.y, c.y));
        vm.z = fmaxf(a.z, fmaxf(b.z, c.z));
        vm.w = fmaxf(a.w, fmaxf(b.w, c.w));
        float vl = __shfl_up_sync(FULLM, vm.w, 1);
        float vr = __shfl_down_sync(FULLM, vm.x, 1);
        if (ledge) vl = NINF;
        if (redge) vr = NINF;
        float4 op;
        op.x = fmaxf(vm.x, fmaxf(vl,   vm.y));
        op.y = fmaxf(vm.y, fmaxf(vm.x, vm.z));
        op.z = fmaxf(vm.z, fmaxf(vm.y, vm.w));
        op.w = fmaxf(vm.w, fmaxf(vm.z, vr));

        const float4 e = L[k][h2];
        float4 d;
        d.x = fmaxf(e.x - op.x, 0.0f);
        d.y = fmaxf(e.y - op.y, 0.0f);
        d.z = fmaxf(e.z - op.z, 0.0f);
        d.w = fmaxf(e.w - op.w, 0.0f);

        float* srow = ring + ((y & 7) << 7) + (lane << 2);
        float4 s;
        if (k == 0) {
            if (INIT) s = make_float4(0.0f, 0.0f, 0.0f, 0.0f);
            else      s = scur;
        } else {
            s = ld4(srow);
        }
        skel_upd(s, d);
        if (k == T - 1) {
            if (outok) {
                skel4[y * ROWQ + gq] = s;
                if (FUSE) {
                    acc_p += s.x * ocur.x + s.y * ocur.y + s.z * ocur.z + s.w * ocur.w;
                    acc_s += s.x + s.y + s.z + s.w;
                }
            }
        } else {
            st4(srow, s);
        }
    }
}

template <int T, bool INIT, bool WRITE_E, bool TOPB, bool BOTB, bool FUSE>
__device__ __forceinline__ void sweep(
    const float4* __restrict__ in4, float4* __restrict__ eout4,
    float4* __restrict__ skel4, const float4* __restrict__ other4,
    float* __restrict__ ring, double* __restrict__ sums, int t_idx,
    int lane, int gq, bool loadok, bool outok, bool ledge, bool redge,
    int b0, int b1)
{
    // NSTEPS >= (b1-b0) + 2T + 4, multiple of 3 (max band = 94 rows)
    constexpr int NST = (T == 6) ? 114 : 108;

    float4 L[T + 1][3];
    const float INF = __int_as_float(0x7f800000);
#pragma unroll
    for (int j = 0; j <= T; ++j)
#pragma unroll
        for (int s = 0; s < 3; ++s)
            L[j][s] = make_float4(INF, INF, INF, INF);

    const int Ys = b0 - (T + 3);

    float4 nxt = make_float4(INF, INF, INF, INF);
    {
        bool ok = loadok;
        if (TOPB) ok = ok && (Ys >= 0);
        if (ok) nxt = in4[Ys * ROWQ + gq];
    }
    float4 snxt = make_float4(0.0f, 0.0f, 0.0f, 0.0f);
    float4 onxt = make_float4(0.0f, 0.0f, 0.0f, 0.0f);
    float acc_p = 0.0f, acc_s = 0.0f;

    for (int d = 0; d < NST; d += 3) {
        do_step<T, 0, INIT, WRITE_E, TOPB, BOTB, FUSE>(Ys + d,     L, nxt, snxt, onxt,
            in4, eout4, skel4, other4, ring, acc_p, acc_s,
            lane, gq, loadok, outok, ledge, redge, b0, b1);
        do_step<T, 1, INIT, WRITE_E, TOPB, BOTB, FUSE>(Ys + d + 1, L, nxt, snxt, onxt,
            in4, eout4, skel4, other4, ring, acc_p, acc_s,
            lane, gq, loadok, outok, ledge, redge, b0, b1);
        do_step<T, 2, INIT, WRITE_E, TOPB, BOTB, FUSE>(Ys + d + 2, L, nxt, snxt, onxt,
            in4, eout4, skel4, other4, ring, acc_p, acc_s,
            lane, gq, loadok, outok, ledge, redge, b0, b1);
    }

    if (FUSE) {
#pragma unroll
        for (int off = 16; off > 0; off >>= 1) {
            acc_p += __shfl_down_sync(FULLM, acc_p, off);
            acc_s += __shfl_down_sync(FULLM, acc_s, off);
        }
        if (lane == 0) {
            atomicAdd(&sums[2 * t_idx],     (double)acc_p);
            atomicAdd(&sums[2 * t_idx + 1], (double)acc_s);
        }
    }
}

// Warp-autonomous erosion tower: no block barriers, 4 blocks/SM (regs capped at 128).
template <int T, bool INIT, bool WRITE_E, bool FUSE>
__global__ __launch_bounds__(128, 4)
void tower(const float* __restrict__ p0, const float* __restrict__ p1,
           const float* __restrict__ o0, const float* __restrict__ o1,
           float* __restrict__ eout, float* __restrict__ gskel)
{
    __shared__ float ring[4][8 * 128];

    const int wid  = threadIdx.x >> 5;
    const int lane = threadIdx.x & 31;
    const int w    = blockIdx.x * 4 + wid;
    const int n    = w / (NBANDS * STRIPS);
    const int rem  = w % (NBANDS * STRIPS);
    const int band = rem / STRIPS;
    const int strip = rem % STRIPS;
    const int b0 = band * BROW0;
    const int b1 = (band == NBANDS - 1) ? IMG_H : (b0 + BROW0);

    const int gq = 26 * strip - 3 + lane;
    const bool loadok = (gq >= 0) && (gq < ROWQ);
    const bool outok  = (lane >= 3) && (lane < 29) && (gq < ROWQ);
    const bool ledge  = (gq == 0);
    const bool redge  = (gq == ROWQ - 1);

    const float* src;
    if (INIT) src = (n < N_IMG) ? (p0 + (size_t)n * IMG_PIX)
                                : (p1 + (size_t)(n - N_IMG) * IMG_PIX);
    else      src = p0 + (size_t)n * IMG_PIX;
    const float* oth = nullptr;
    const int t_idx = (n >= N_IMG) ? 1 : 0;
    if (FUSE) oth = (n < N_IMG) ? (o0 + (size_t)n * IMG_PIX)
                                : (o1 + (size_t)(n - N_IMG) * IMG_PIX);

    const float4* in4   = (const float4*)src;
    float4*       eout4 = (float4*)(WRITE_E ? (eout + (size_t)n * IMG_PIX) : nullptr);
    float4*       skel4 = (float4*)(gskel + (size_t)n * IMG_PIX);
    const float4* oth4  = (const float4*)oth;
    float* myring = &ring[wid][0];

    if (band == 0)
        sweep<T, INIT, WRITE_E, true,  false, FUSE>(in4, eout4, skel4, oth4, myring, g_sums,
            t_idx, lane, gq, loadok, outok, ledge, redge, b0, b1);
    else if (band == NBANDS - 1)
        sweep<T, INIT, WRITE_E, false, true,  FUSE>(in4, eout4, skel4, oth4, myring, g_sums,
            t_idx, lane, gq, loadok, outok, ledge, redge, b0, b1);
    else
        sweep<T, INIT, WRITE_E, false, false, FUSE>(in4, eout4, skel4, oth4, myring, g_sums,
            t_idx, lane, gq, loadok, outok, ledge, redge, b0, b1);
}

__global__ void zero_sums(double* sums) {
    if (threadIdx.x < 4) sums[threadIdx.x] = 0.0;
}

__global__ void finalize_cldice(const double* __restrict__ sums, float* __restrict__ out) {
    const double tprec = (sums[0] + SMOOTH) / (sums[1] + SMOOTH);
    const double tsens = (sums[2] + SMOOTH) / (sums[3] + SMOOTH);
    out[0] = (float)(1.0 - 2.0 * (tprec * tsens) / (tprec + tsens));
}

extern "C" void kernel_launch(void* const* d_in, const int* in_sizes, int n_in,
                              void* d_out, int out_size) {
    const float* target = (const float*)d_in[0];
    const float* inputs = (const float*)d_in[1];
    float* out = (float*)d_out;

    static float* bufA = nullptr;
    static float* bufB = nullptr;
    static float* skel = nullptr;
    static double* sums = nullptr;
    if (!bufA) {
        cudaGetSymbolAddress((void**)&bufA, g_bufA);
        cudaGetSymbolAddress((void**)&bufB, g_bufB);
        cudaGetSymbolAddress((void**)&skel, g_skel);
        cudaGetSymbolAddress((void**)&sums, g_sums);
    }

    // warps: 64 images x 11 bands x 10 strips = 7040 -> 1760 blocks x 4 warps
    // (4 blocks/SM -> 592 slots -> 2.97 waves, 99% packed)
    const int NBLK = (2 * N_IMG * NBANDS * STRIPS) / 4;
    const dim3 block(128);

    zero_sums<<<1, 32>>>(sums);

    // Erosion tower E_0..E_26, deltas 0..25: passes T = 6,5,5,5,5.
    // Last pass fuses the skel/other reduction.
    tower<6, true,  true,  false><<<NBLK, block>>>(inputs, target, nullptr, nullptr, bufA, skel);
    tower<5, false, true,  false><<<NBLK, block>>>(bufA, nullptr, nullptr, nullptr, bufB, skel);
    tower<5, false, true,  false><<<NBLK, block>>>(bufB, nullptr, nullptr, nullptr, bufA, skel);
    tower<5, false, true,  false><<<NBLK, block>>>(bufA, nullptr, nullptr, nullptr, bufB, skel);
    tower<5, false, false, true ><<<NBLK, block>>>(bufB, nullptr, target, inputs, nullptr, skel);

    finalize_cldice<<<1, 1>>>(sums, out);
}

// round 12
// speedup vs baseline: 1.5485x; 1.0771x over previous
#include <cuda_runtime.h>
#include <cstdint>

#define IMG_W   1024
#define IMG_H   1024
#define IMG_PIX (IMG_W * IMG_H)
#define N_IMG   32
#define TOTAL_F ((size_t)N_IMG * IMG_PIX)
#define SMOOTH  1e-5
#define FULLM   0xffffffffu
#define NBANDS  11                    // bands 0..9: 93 rows; band 10: 94 rows
#define BROW0   93
#define STRIPS  10
#define ROWQ    (IMG_W / 4)

// Scratch (no cudaMalloc allowed)
__device__ float g_bufA[2 * N_IMG * IMG_PIX];
__device__ float g_bufB[2 * N_IMG * IMG_PIX];
__device__ float g_skel[2 * N_IMG * IMG_PIX];
__device__ double g_sums[4];

__device__ __forceinline__ float4 ld4(const float* p) { return *(const float4*)p; }
__device__ __forceinline__ void st4(float* p, float4 v) { *(float4*)p = v; }

__device__ __forceinline__ void skel_upd(float4& s, const float4& d) {
    s.x += fmaxf(fmaf(-s.x, d.x, d.x), 0.0f);
    s.y += fmaxf(fmaf(-s.y, d.y, d.y), 0.0f);
    s.z += fmaxf(fmaf(-s.z, d.z, d.z), 0.0f);
    s.w += fmaxf(fmaf(-s.w, d.w, d.w), 0.0f);
}

// One sweep step at row Y, ring slot U (compile-time).
// Ring invariant after step Y: L[j][U] = level-j row (Y-j); (U+2)%3 = that row-1; (U+1)%3 = row-2.
// Pointers inP/skP/otP/eoP are maintained at "row Y" after the top-of-step increment;
// all row accesses are compile-time offsets from them (strength-reduced addressing).
template <int T, int U, bool INIT, bool WRITE_E, bool TOPB, bool BOTB, bool FUSE>
__device__ __forceinline__ void do_step(
    int Y, float4 (&L)[T + 1][3], float4& nxt, float4& snxt, float4& onxt,
    const float4*& inP, float4*& skP, const float4*& otP, float4*& eoP,
    float* __restrict__ ring, float& acc_p, float& acc_s,
    int lane, bool loadok, bool outok, bool ledge, bool redge,
    int b0, int b1)
{
    const float INF  = __int_as_float(0x7f800000);
    const float NINF = -INF;
    constexpr int u  = U;
    constexpr int h1 = (U + 2) % 3;
    constexpr int h2 = (U + 1) % 3;

    // Advance stream pointers to row Y.
    inP += ROWQ;
    skP += ROWQ;
    if (FUSE) otP += ROWQ;
    if (WRITE_E) eoP += ROWQ;

    // Consume prefetched input row Y; prefetch row Y+1 (offset +ROWQ).
    L[0][u] = nxt;
    {
        const int yy = Y + 1;
        bool ok = loadok;
        if (TOPB) ok = ok && (yy >= 0);
        if (BOTB) ok = ok && (yy < IMG_H);
        float4 v = make_float4(INF, INF, INF, INF);
        if (ok) v = inP[ROWQ];
        nxt = v;
    }
    // Consume prefetched skel row (Y-2); prefetch row Y-1 (offset -ROWQ).
    float4 scur = snxt;
    if (!INIT) {
        const int yy = Y - 1;
        float4 sv = make_float4(0.0f, 0.0f, 0.0f, 0.0f);
        if (yy >= b0 && yy < b1 && outok) sv = skP[-ROWQ];
        snxt = sv;
    }
    // Consume prefetched other row (Y-T-1); prefetch row Y-T (offset -T*ROWQ).
    float4 ocur = onxt;
    if (FUSE) {
        const int yy = Y - T;
        float4 ov = make_float4(0.0f, 0.0f, 0.0f, 0.0f);
        if (yy >= b0 && yy < b1 && outok) ov = otP[-T * ROWQ];
        onxt = ov;
    }

    // Erosion levels: level j computes row r = Y - j from level j-1 rows r-1..r+1
#pragma unroll
    for (int j = 1; j <= T; ++j) {
        const int r = Y - j;
        const float4 up = L[j - 1][h2];
        const float4 ce = L[j - 1][h1];
        const float4 dn = L[j - 1][u];
        const float cl = __shfl_up_sync(FULLM, ce.w, 1);
        const float cr = __shfl_down_sync(FULLM, ce.x, 1);
        float4 o;
        o.x = fminf(fminf(fminf(up.x, dn.x), fminf(cl,   ce.y)), ce.x);
        o.y = fminf(fminf(fminf(up.y, dn.y), fminf(ce.x, ce.z)), ce.y);
        o.z = fminf(fminf(fminf(up.z, dn.z), fminf(ce.y, ce.w)), ce.z);
        o.w = fminf(fminf(fminf(up.w, dn.w), fminf(ce.z, cr  )), ce.w);
        if (TOPB) { if (r < 0)      o = make_float4(INF, INF, INF, INF); }
        if (BOTB) { if (r >= IMG_H) o = make_float4(INF, INF, INF, INF); }
        L[j][u] = o;
        if (WRITE_E && j == T) {
            if (r >= b0 && r < b1 && outok) eoP[-T * ROWQ] = o;   // row Y - T
        }
    }

    // Deltas: delta_k at row y = Y - k - 2
#pragma unroll
    for (int k = 0; k < T; ++k) {
        const int y = Y - k - 2;
        if (y < b0 || y >= b1) continue;

        float4 a = L[k + 1][h2];
        const float4 b = L[k + 1][h1];
        float4 c = L[k + 1][u];
        if (TOPB) { if (y == 0)         a = make_float4(NINF, NINF, NINF, NINF); }
        if (BOTB) { if (y == IMG_H - 1) c = make_float4(NINF, NINF, NINF, NINF); }

        float4 vm;
        vm.x = fmaxf(a.x, fmaxf(b.x, c.x));
        vm.y = fmaxf(a.y, fmaxf(b.y, c.y));
        vm.z = fmaxf(a.z, fmaxf(b.z, c.z));
        vm.w = fmaxf(a.w, fmaxf(b.w, c.w));
        float vl = __shfl_up_sync(FULLM, vm.w, 1);
        float vr = __shfl_down_sync(FULLM, vm.x, 1);
        if (ledge) vl = NINF;
        if (redge) vr = NINF;
        float4 op;
        op.x = fmaxf(vm.x, fmaxf(vl,   vm.y));
        op.y = fmaxf(vm.y, fmaxf(vm.x, vm.z));
        op.z = fmaxf(vm.z, fmaxf(vm.y, vm.w));
        op.w = fmaxf(vm.w, fmaxf(vm.z, vr));

        const float4 e = L[k][h2];
        float4 d;
        d.x = fmaxf(e.x - op.x, 0.0f);
        d.y = fmaxf(e.y - op.y, 0.0f);
        d.z = fmaxf(e.z - op.z, 0.0f);
        d.w = fmaxf(e.w - op.w, 0.0f);

        float* srow = ring + ((y & 7) << 7) + (lane << 2);
        float4 s;
        if (k == 0) {
            if (INIT) s = make_float4(0.0f, 0.0f, 0.0f, 0.0f);
            else      s = scur;
        } else {
            s = ld4(srow);
        }
        skel_upd(s, d);
        if (k == T - 1) {
            if (outok) {
                skP[-(T + 1) * ROWQ] = s;                 // row Y - T - 1
                if (FUSE) {
                    acc_p += s.x * ocur.x + s.y * ocur.y + s.z * ocur.z + s.w * ocur.w;
                    acc_s += s.x + s.y + s.z + s.w;
                }
            }
        } else {
            st4(srow, s);
        }
    }
}

template <int T, bool INIT, bool WRITE_E, bool TOPB, bool BOTB, bool FUSE>
__device__ __forceinline__ void sweep(
    const float4* __restrict__ in4, float4* __restrict__ eout4,
    float4* __restrict__ skel4, const float4* __restrict__ other4,
    float* __restrict__ ring, double* __restrict__ sums, int t_idx,
    int lane, int gq, bool loadok, bool outok, bool ledge, bool redge,
    int b0, int b1)
{
    // NSTEPS >= (b1-b0) + 2T + 4, multiple of 3 (max band = 94 rows)
    constexpr int NST = (T == 6) ? 111 : 108;

    float4 L[T + 1][3];
    const float INF = __int_as_float(0x7f800000);
#pragma unroll
    for (int j = 0; j <= T; ++j)
#pragma unroll
        for (int s = 0; s < 3; ++s)
            L[j][s] = make_float4(INF, INF, INF, INF);

    const int Ys = b0 - (T + 3);

    // Stream pointers at "row Ys-1"; first do_step advances them to row Ys.
    const float4* inP = in4   + (Ys - 1) * ROWQ + gq;
    float4*       skP = skel4 + (Ys - 1) * ROWQ + gq;
    const float4* otP = FUSE    ? (other4 + (Ys - 1) * ROWQ + gq) : nullptr;
    float4*       eoP = WRITE_E ? (eout4  + (Ys - 1) * ROWQ + gq) : nullptr;

    float4 nxt = make_float4(INF, INF, INF, INF);
    {
        bool ok = loadok;
        if (TOPB) ok = ok && (Ys >= 0);
        if (ok) nxt = in4[Ys * ROWQ + gq];
    }
    float4 snxt = make_float4(0.0f, 0.0f, 0.0f, 0.0f);
    float4 onxt = make_float4(0.0f, 0.0f, 0.0f, 0.0f);
    float acc_p = 0.0f, acc_s = 0.0f;

    for (int d = 0; d < NST; d += 3) {
        do_step<T, 0, INIT, WRITE_E, TOPB, BOTB, FUSE>(Ys + d,     L, nxt, snxt, onxt,
            inP, skP, otP, eoP, ring, acc_p, acc_s,
            lane, loadok, outok, ledge, redge, b0, b1);
        do_step<T, 1, INIT, WRITE_E, TOPB, BOTB, FUSE>(Ys + d + 1, L, nxt, snxt, onxt,
            inP, skP, otP, eoP, ring, acc_p, acc_s,
            lane, loadok, outok, ledge, redge, b0, b1);
        do_step<T, 2, INIT, WRITE_E, TOPB, BOTB, FUSE>(Ys + d + 2, L, nxt, snxt, onxt,
            inP, skP, otP, eoP, ring, acc_p, acc_s,
            lane, loadok, outok, ledge, redge, b0, b1);
    }

    if (FUSE) {
#pragma unroll
        for (int off = 16; off > 0; off >>= 1) {
            acc_p += __shfl_down_sync(FULLM, acc_p, off);
            acc_s += __shfl_down_sync(FULLM, acc_s, off);
        }
        if (lane == 0) {
            atomicAdd(&sums[2 * t_idx],     (double)acc_p);
            atomicAdd(&sums[2 * t_idx + 1], (double)acc_s);
        }
    }
}

// Warp-autonomous erosion tower: no block barriers, 4 blocks/SM (regs capped at 128).
template <int T, bool INIT, bool WRITE_E, bool FUSE>
__global__ __launch_bounds__(128, 4)
void tower(const float* __restrict__ p0, const float* __restrict__ p1,
           const float* __restrict__ o0, const float* __restrict__ o1,
           float* __restrict__ eout, float* __restrict__ gskel)
{
    __shared__ float ring[4][8 * 128];

    const int wid  = threadIdx.x >> 5;
    const int lane = threadIdx.x & 31;
    const int w    = blockIdx.x * 4 + wid;
    const int n    = w / (NBANDS * STRIPS);
    const int rem  = w % (NBANDS * STRIPS);
    const int band = rem / STRIPS;
    const int strip = rem % STRIPS;
    const int b0 = band * BROW0;
    const int b1 = (band == NBANDS - 1) ? IMG_H : (b0 + BROW0);

    const int gq = 26 * strip - 3 + lane;
    const bool loadok = (gq >= 0) && (gq < ROWQ);
    const bool outok  = (lane >= 3) && (lane < 29) && (gq < ROWQ);
    const bool ledge  = (gq == 0);
    const bool redge  = (gq == ROWQ - 1);

    const float* src;
    if (INIT) src = (n < N_IMG) ? (p0 + (size_t)n * IMG_PIX)
                                : (p1 + (size_t)(n - N_IMG) * IMG_PIX);
    else      src = p0 + (size_t)n * IMG_PIX;
    const float* oth = nullptr;
    const int t_idx = (n >= N_IMG) ? 1 : 0;
    if (FUSE) oth = (n < N_IMG) ? (o0 + (size_t)n * IMG_PIX)
                                : (o1 + (size_t)(n - N_IMG) * IMG_PIX);

    const float4* in4   = (const float4*)src;
    float4*       eout4 = (float4*)(WRITE_E ? (eout + (size_t)n * IMG_PIX) : nullptr);
    float4*       skel4 = (float4*)(gskel + (size_t)n * IMG_PIX);
    const float4* oth4  = (const float4*)oth;
    float* myring = &ring[wid][0];

    if (band == 0)
        sweep<T, INIT, WRITE_E, true,  false, FUSE>(in4, eout4, skel4, oth4, myring, g_sums,
            t_idx, lane, gq, loadok, outok, ledge, redge, b0, b1);
    else if (band == NBANDS - 1)
        sweep<T, INIT, WRITE_E, false, true,  FUSE>(in4, eout4, skel4, oth4, myring, g_sums,
            t_idx, lane, gq, loadok, outok, ledge, redge, b0, b1);
    else
        sweep<T, INIT, WRITE_E, false, false, FUSE>(in4, eout4, skel4, oth4, myring, g_sums,
            t_idx, lane, gq, loadok, outok, ledge, redge, b0, b1);
}

__global__ void zero_sums(double* sums) {
    if (threadIdx.x < 4) sums[threadIdx.x] = 0.0;
}

__global__ void finalize_cldice(const double* __restrict__ sums, float* __restrict__ out) {
    const double tprec = (sums[0] + SMOOTH) / (sums[1] + SMOOTH);
    const double tsens = (sums[2] + SMOOTH) / (sums[3] + SMOOTH);
    out[0] = (float)(1.0 - 2.0 * (tprec * tsens) / (tprec + tsens));
}

extern "C" void kernel_launch(void* const* d_in, const int* in_sizes, int n_in,
                              void* d_out, int out_size) {
    const float* target = (const float*)d_in[0];
    const float* inputs = (const float*)d_in[1];
    float* out = (float*)d_out;

    static float* bufA = nullptr;
    static float* bufB = nullptr;
    static float* skel = nullptr;
    static double* sums = nullptr;
    if (!bufA) {
        cudaGetSymbolAddress((void**)&bufA, g_bufA);
        cudaGetSymbolAddress((void**)&bufB, g_bufB);
        cudaGetSymbolAddress((void**)&skel, g_skel);
        cudaGetSymbolAddress((void**)&sums, g_sums);
    }

    // warps: 64 images x 11 bands x 10 strips = 7040 -> 1760 blocks x 4 warps
    // (4 blocks/SM -> 592 slots -> 2.97 waves)
    const int NBLK = (2 * N_IMG * NBANDS * STRIPS) / 4;
    const dim3 block(128);

    zero_sums<<<1, 32>>>(sums);

    // Erosion tower E_0..E_26, deltas 0..25: passes T = 6,5,5,5,5.
    // Last pass fuses the skel/other reduction.
    tower<6, true,  true,  false><<<NBLK, block>>>(inputs, target, nullptr, nullptr, bufA, skel);
    tower<5, false, true,  false><<<NBLK, block>>>(bufA, nullptr, nullptr, nullptr, bufB, skel);
    tower<5, false, true,  false><<<NBLK, block>>>(bufB, nullptr, nullptr, nullptr, bufA, skel);
    tower<5, false, true,  false><<<NBLK, block>>>(bufA, nullptr, nullptr, nullptr, bufB, skel);
    tower<5, false, false, true ><<<NBLK, block>>>(bufB, nullptr, target, inputs, nullptr, skel);

    finalize_cldice<<<1, 1>>>(sums, out);
}

// round 13
// speedup vs baseline: 1.8282x; 1.1806x over previous
#include <cuda_runtime.h>
#include <cuda_fp16.h>
#include <cstdint>

#define IMG_W   1024
#define IMG_H   1024
#define IMG_PIX (IMG_W * IMG_H)
#define N_IMG   32
#define TOTAL_F ((size_t)N_IMG * IMG_PIX)
#define SMOOTH  1e-5
#define FULLM   0xffffffffu
#define NBANDS  11                    // bands 0..9: 93 rows; band 10: 94 rows
#define BROW0   93
#define STRIPS  10
#define ROWQ    (IMG_W / 4)           // quads (4 cols) per row

typedef __half2 h2;
struct HQ { h2 p, q; };               // 4 columns: p=(c0,c1), q=(c2,c3)

// Scratch (no cudaMalloc allowed): fp16 intermediates
__device__ __half g_bufA[2 * N_IMG * IMG_PIX];
__device__ __half g_bufB[2 * N_IMG * IMG_PIX];
__device__ __half g_skel[2 * N_IMG * IMG_PIX];
__device__ double g_sums[4];

__device__ __forceinline__ HQ mkHQ(h2 a, h2 b) { HQ r; r.p = a; r.q = b; return r; }
__device__ __forceinline__ h2 hc(unsigned short u) { return __half2half2(__ushort_as_half(u)); }
__device__ __forceinline__ HQ ldHQ(const uint2* p) {
    uint2 u = *p; HQ v;
    v.p = *(h2*)&u.x; v.q = *(h2*)&u.y; return v;
}
__device__ __forceinline__ void stHQ(uint2* p, HQ v) {
    uint2 u; u.x = *(unsigned*)&v.p; u.y = *(unsigned*)&v.q; *p = u;
}
__device__ __forceinline__ h2 shup(h2 v) {
    unsigned u = *(unsigned*)&v; u = __shfl_up_sync(FULLM, u, 1); return *(h2*)&u;
}
__device__ __forceinline__ h2 shdn(h2 v) {
    unsigned u = *(unsigned*)&v; u = __shfl_down_sync(FULLM, u, 1); return *(h2*)&u;
}

// One sweep step at row Y, ring slot U (compile-time). fp16 tower.
// Ring invariant after step Y: L[j][U] = level-j row (Y-j); (U+2)%3 = that row-1; (U+1)%3 = row-2.
template <int T, int U, bool INIT, bool WRITE_E, bool TOPB, bool BOTB, bool FUSE>
__device__ __forceinline__ void do_step(
    int Y, HQ (&L)[T + 1][3], HQ& nxt, HQ& snxt, float4& onxt,
    const float4*& inPf, const uint2*& inPh, uint2*& skP, const float4*& otP, uint2*& eoP,
    uint2* __restrict__ ring, float& acc_p, float& acc_s,
    int lane, bool loadok, bool outok, bool ledge, bool redge,
    int b0, int b1)
{
    const h2 INF2  = hc(0x7C00);
    const h2 NINF2 = hc(0xFC00);
    const h2 ZERO2 = hc(0x0000);
    const __half NINFh = __ushort_as_half(0xFC00);
    constexpr int u  = U;
    constexpr int h1 = (U + 2) % 3;
    constexpr int hh2 = (U + 1) % 3;

    // Advance stream pointers to row Y.
    if (INIT) inPf += ROWQ; else inPh += ROWQ;
    skP += ROWQ;
    if (FUSE) otP += ROWQ;
    if (WRITE_E) eoP += ROWQ;

    // Consume prefetched input row Y; prefetch row Y+1.
    L[0][u] = nxt;
    {
        const int yy = Y + 1;
        bool ok = loadok;
        if (TOPB) ok = ok && (yy >= 0);
        if (BOTB) ok = ok && (yy < IMG_H);
        HQ v = mkHQ(INF2, INF2);
        if (ok) {
            if (INIT) {
                float4 f = inPf[ROWQ];
                v.p = __floats2half2_rn(f.x, f.y);
                v.q = __floats2half2_rn(f.z, f.w);
            } else {
                v = ldHQ(inPh + ROWQ);
            }
        }
        nxt = v;
    }
    // Consume prefetched skel row (Y-2); prefetch row Y-1.
    HQ scur = snxt;
    if (!INIT) {
        const int yy = Y - 1;
        HQ sv = mkHQ(ZERO2, ZERO2);
        if (yy >= b0 && yy < b1 && outok) sv = ldHQ(skP - ROWQ);
        snxt = sv;
    }
    // Consume prefetched other row (Y-T-1, fp32); prefetch row Y-T.
    float4 ocur = onxt;
    if (FUSE) {
        const int yy = Y - T;
        float4 ov = make_float4(0.0f, 0.0f, 0.0f, 0.0f);
        if (yy >= b0 && yy < b1 && outok) ov = otP[-T * ROWQ];
        onxt = ov;
    }

    // Erosion levels: level j computes row r = Y - j from level j-1 rows r-1..r+1
#pragma unroll
    for (int j = 1; j <= T; ++j) {
        const int r = Y - j;
        const HQ up = L[j - 1][hh2];
        const HQ ce = L[j - 1][h1];
        const HQ dn = L[j - 1][u];
        const h2 lf = shup(ce.q);   // left neighbor's (c2,c3)
        const h2 rt = shdn(ce.p);   // right neighbor's (c0,c1)
        const h2 mid = __halves2half2(__high2half(ce.p), __low2half(ce.q));  // (c1,c2)
        const h2 lv  = __halves2half2(__high2half(lf),   __low2half(ce.p));  // (cl,c0)
        const h2 rv  = __halves2half2(__high2half(ce.q), __low2half(rt));    // (c3,cr)
        HQ o;
        o.p = __hmin2(__hmin2(__hmin2(up.p, dn.p), ce.p), __hmin2(lv,  mid));
        o.q = __hmin2(__hmin2(__hmin2(up.q, dn.q), ce.q), __hmin2(mid, rv));
        if (TOPB) { if (r < 0)      o = mkHQ(INF2, INF2); }
        if (BOTB) { if (r >= IMG_H) o = mkHQ(INF2, INF2); }
        L[j][u] = o;
        if (WRITE_E && j == T) {
            if (r >= b0 && r < b1 && outok) stHQ(eoP - T * ROWQ, o);   // row Y-T
        }
    }

    // Deltas: delta_k at row y = Y - k - 2
#pragma unroll
    for (int k = 0; k < T; ++k) {
        const int y = Y - k - 2;
        if (y < b0 || y >= b1) continue;

        HQ A = L[k + 1][hh2];
        const HQ B = L[k + 1][h1];
        HQ C = L[k + 1][u];
        if (TOPB) { if (y == 0)         A = mkHQ(NINF2, NINF2); }
        if (BOTB) { if (y == IMG_H - 1) C = mkHQ(NINF2, NINF2); }

        const h2 vmP = __hmax2(__hmax2(A.p, B.p), C.p);
        const h2 vmQ = __hmax2(__hmax2(A.q, B.q), C.q);
        const h2 lf = shup(vmQ);
        const h2 rt = shdn(vmP);
        const h2 mid = __halves2half2(__high2half(vmP), __low2half(vmQ));
        const h2 lv  = __halves2half2(ledge ? NINFh : __high2half(lf), __low2half(vmP));
        const h2 rv  = __halves2half2(__high2half(vmQ), redge ? NINFh : __low2half(rt));
        const h2 opP = __hmax2(vmP, __hmax2(lv,  mid));
        const h2 opQ = __hmax2(vmQ, __hmax2(mid, rv));

        const HQ e = L[k][hh2];
        const h2 dP = __hmax2(__hsub2(e.p, opP), ZERO2);
        const h2 dQ = __hmax2(__hsub2(e.q, opQ), ZERO2);

        uint2* srow = ring + ((y & 7) << 5) + lane;
        HQ s;
        if (k == 0) {
            if (INIT) s = mkHQ(ZERO2, ZERO2);
            else      s = scur;
        } else {
            s = ldHQ(srow);
        }
        // s += relu(d - s*d) = s + max(fma(-s, d, d), 0)
        s.p = __hadd2(s.p, __hmax2(__hfma2(__hneg2(s.p), dP, dP), ZERO2));
        s.q = __hadd2(s.q, __hmax2(__hfma2(__hneg2(s.q), dQ, dQ), ZERO2));

        if (k == T - 1) {
            if (outok) {
                if (FUSE) {
                    const float2 f0 = __half22float2(s.p);
                    const float2 f1 = __half22float2(s.q);
                    acc_p += f0.x * ocur.x + f0.y * ocur.y + f1.x * ocur.z + f1.y * ocur.w;
                    acc_s += f0.x + f0.y + f1.x + f1.y;
                } else {
                    stHQ(skP - (T + 1) * ROWQ, s);        // row Y-T-1
                }
            }
        } else {
            stHQ(srow, s);
        }
    }
}

template <int T, bool INIT, bool WRITE_E, bool TOPB, bool BOTB, bool FUSE>
__device__ __forceinline__ void sweep(
    const float4* in4f, const uint2* in2h, uint2* eout2,
    uint2* skel2, const float4* other4,
    uint2* __restrict__ ring, double* __restrict__ sums, int t_idx,
    int lane, int gq, bool loadok, bool outok, bool ledge, bool redge,
    int b0, int b1)
{
    // NSTEPS >= (b1-b0) + 2T + 4, multiple of 3 (max band = 94 rows)
    constexpr int NST = (T == 6) ? 111 : 108;
    const h2 INF2  = hc(0x7C00);
    const h2 ZERO2 = hc(0x0000);

    HQ L[T + 1][3];
#pragma unroll
    for (int j = 0; j <= T; ++j)
#pragma unroll
        for (int s = 0; s < 3; ++s)
            L[j][s] = mkHQ(INF2, INF2);

    const int Ys = b0 - (T + 3);

    // Stream pointers at "row Ys-1"; first do_step advances them to row Ys.
    const float4* inPf = INIT    ? (in4f   + (Ys - 1) * ROWQ + gq) : nullptr;
    const uint2*  inPh = !INIT   ? (in2h   + (Ys - 1) * ROWQ + gq) : nullptr;
    uint2*        skP  = skel2   + (Ys - 1) * ROWQ + gq;
    const float4* otP  = FUSE    ? (other4 + (Ys - 1) * ROWQ + gq) : nullptr;
    uint2*        eoP  = WRITE_E ? (eout2  + (Ys - 1) * ROWQ + gq) : nullptr;

    HQ nxt = mkHQ(INF2, INF2);
    {
        bool ok = loadok;
        if (TOPB) ok = ok && (Ys >= 0);
        if (ok) {
            if (INIT) {
                float4 f = in4f[Ys * ROWQ + gq];
                nxt.p = __floats2half2_rn(f.x, f.y);
                nxt.q = __floats2half2_rn(f.z, f.w);
            } else {
                nxt = ldHQ(in2h + Ys * ROWQ + gq);
            }
        }
    }
    HQ snxt = mkHQ(ZERO2, ZERO2);
    float4 onxt = make_float4(0.0f, 0.0f, 0.0f, 0.0f);
    float acc_p = 0.0f, acc_s = 0.0f;

    for (int d = 0; d < NST; d += 3) {
        do_step<T, 0, INIT, WRITE_E, TOPB, BOTB, FUSE>(Ys + d,     L, nxt, snxt, onxt,
            inPf, inPh, skP, otP, eoP, ring, acc_p, acc_s,
            lane, loadok, outok, ledge, redge, b0, b1);
        do_step<T, 1, INIT, WRITE_E, TOPB, BOTB, FUSE>(Ys + d + 1, L, nxt, snxt, onxt,
            inPf, inPh, skP, otP, eoP, ring, acc_p, acc_s,
            lane, loadok, outok, ledge, redge, b0, b1);
        do_step<T, 2, INIT, WRITE_E, TOPB, BOTB, FUSE>(Ys + d + 2, L, nxt, snxt, onxt,
            inPf, inPh, skP, otP, eoP, ring, acc_p, acc_s,
            lane, loadok, outok, ledge, redge, b0, b1);
    }

    if (FUSE) {
#pragma unroll
        for (int off = 16; off > 0; off >>= 1) {
            acc_p += __shfl_down_sync(FULLM, acc_p, off);
            acc_s += __shfl_down_sync(FULLM, acc_s, off);
        }
        if (lane == 0) {
            atomicAdd(&sums[2 * t_idx],     (double)acc_p);
            atomicAdd(&sums[2 * t_idx + 1], (double)acc_s);
        }
    }
}

// Warp-autonomous erosion tower: no block barriers. fp16 tower data.
template <int T, bool INIT, bool WRITE_E, bool FUSE>
__global__ __launch_bounds__(128, 5)
void tower(const float* __restrict__ p0, const float* __restrict__ p1,
           const float* __restrict__ o0, const float* __restrict__ o1,
           const __half* __restrict__ hin, __half* __restrict__ eout,
           __half* __restrict__ gskel)
{
    __shared__ uint2 ring[4][8 * 32];

    const int wid  = threadIdx.x >> 5;
    const int lane = threadIdx.x & 31;
    const int w    = blockIdx.x * 4 + wid;
    const int n    = w / (NBANDS * STRIPS);
    const int rem  = w % (NBANDS * STRIPS);
    const int band = rem / STRIPS;
    const int strip = rem % STRIPS;
    const int b0 = band * BROW0;
    const int b1 = (band == NBANDS - 1) ? IMG_H : (b0 + BROW0);

    const int gq = 26 * strip - 3 + lane;
    const bool loadok = (gq >= 0) && (gq < ROWQ);
    const bool outok  = (lane >= 3) && (lane < 29) && (gq < ROWQ);
    const bool ledge  = (gq == 0);
    const bool redge  = (gq == ROWQ - 1);

    const float* srcf = nullptr;
    if (INIT) srcf = (n < N_IMG) ? (p0 + (size_t)n * IMG_PIX)
                                 : (p1 + (size_t)(n - N_IMG) * IMG_PIX);
    const __half* srch = INIT ? nullptr : (hin + (size_t)n * IMG_PIX);
    const float* oth = nullptr;
    const int t_idx = (n >= N_IMG) ? 1 : 0;
    if (FUSE) oth = (n < N_IMG) ? (o0 + (size_t)n * IMG_PIX)
                                : (o1 + (size_t)(n - N_IMG) * IMG_PIX);

    const float4* in4f  = (const float4*)srcf;
    const uint2*  in2h  = (const uint2*)srch;
    uint2*        eout2 = (uint2*)(WRITE_E ? (eout + (size_t)n * IMG_PIX) : nullptr);
    uint2*        skel2 = (uint2*)(gskel + (size_t)n * IMG_PIX);
    const float4* oth4  = (const float4*)oth;
    uint2* myring = &ring[wid][0];

    if (band == 0)
        sweep<T, INIT, WRITE_E, true,  false, FUSE>(in4f, in2h, eout2, skel2, oth4, myring,
            g_sums, t_idx, lane, gq, loadok, outok, ledge, redge, b0, b1);
    else if (band == NBANDS - 1)
        sweep<T, INIT, WRITE_E, false, true,  FUSE>(in4f, in2h, eout2, skel2, oth4, myring,
            g_sums, t_idx, lane, gq, loadok, outok, ledge, redge, b0, b1);
    else
        sweep<T, INIT, WRITE_E, false, false, FUSE>(in4f, in2h, eout2, skel2, oth4, myring,
            g_sums, t_idx, lane, gq, loadok, outok, ledge, redge, b0, b1);
}

__global__ void zero_sums(double* sums) {
    if (threadIdx.x < 4) sums[threadIdx.x] = 0.0;
}

__global__ void finalize_cldice(const double* __restrict__ sums, float* __restrict__ out) {
    const double tprec = (sums[0] + SMOOTH) / (sums[1] + SMOOTH);
    const double tsens = (sums[2] + SMOOTH) / (sums[3] + SMOOTH);
    out[0] = (float)(1.0 - 2.0 * (tprec * tsens) / (tprec + tsens));
}

extern "C" void kernel_launch(void* const* d_in, const int* in_sizes, int n_in,
                              void* d_out, int out_size) {
    const float* target = (const float*)d_in[0];
    const float* inputs = (const float*)d_in[1];
    float* out = (float*)d_out;

    static __half* bufA = nullptr;
    static __half* bufB = nullptr;
    static __half* skel = nullptr;
    static double* sums = nullptr;
    if (!bufA) {
        cudaGetSymbolAddress((void**)&bufA, g_bufA);
        cudaGetSymbolAddress((void**)&bufB, g_bufB);
        cudaGetSymbolAddress((void**)&skel, g_skel);
        cudaGetSymbolAddress((void**)&sums, g_sums);
    }

    // warps: 64 images x 11 bands x 10 strips = 7040 -> 1760 blocks x 4 warps
    const int NBLK = (2 * N_IMG * NBANDS * STRIPS) / 4;
    const dim3 block(128);

    zero_sums<<<1, 32>>>(sums);

    // Erosion tower E_0..E_26, deltas 0..25: passes T = 6,5,5,5,5 (fp16).
    // Pass 1 converts fp32->fp16; last pass fuses the skel/other reduction.
    tower<6, true,  true,  false><<<NBLK, block>>>(inputs, target, nullptr, nullptr,
                                                   nullptr, bufA, skel);
    tower<5, false, true,  false><<<NBLK, block>>>(nullptr, nullptr, nullptr, nullptr,
                                                   bufA, bufB, skel);
    tower<5, false, true,  false><<<NBLK, block>>>(nullptr, nullptr, nullptr, nullptr,
                                                   bufB, bufA, skel);
    tower<5, false, true,  false><<<NBLK, block>>>(nullptr, nullptr, nullptr, nullptr,
                                                   bufA, bufB, skel);
    tower<5, false, false, true ><<<NBLK, block>>>(nullptr, nullptr, target, inputs,
                                                   bufB, nullptr, skel);

    finalize_cldice<<<1, 1>>>(sums, out);
}

// round 14
// speedup vs baseline: 1.9265x; 1.0538x over previous
#include <cuda_runtime.h>
#include <cuda_fp16.h>
#include <cstdint>

#define IMG_W   1024
#define IMG_H   1024
#define IMG_PIX (IMG_W * IMG_H)
#define N_IMG   32
#define TOTAL_F ((size_t)N_IMG * IMG_PIX)
#define SMOOTH  1e-5
#define FULLM   0xffffffffu
#define NBANDS  11                    // bands 0..9: 93 rows; band 10: 94 rows
#define BROW0   93
#define STRIPS  10
#define ROWQ    (IMG_W / 4)           // quads (4 cols) per row

typedef __half2 h2;
struct HQ { h2 p, q; };               // 4 columns: p=(c0,c1), q=(c2,c3)

// Scratch (no cudaMalloc allowed): fp16 intermediates
__device__ __half g_bufA[2 * N_IMG * IMG_PIX];
__device__ __half g_bufB[2 * N_IMG * IMG_PIX];
__device__ __half g_skel[2 * N_IMG * IMG_PIX];
__device__ double g_sums[4];

__device__ __forceinline__ HQ mkHQ(h2 a, h2 b) { HQ r; r.p = a; r.q = b; return r; }
__device__ __forceinline__ h2 hc(unsigned short u) { return __half2half2(__ushort_as_half(u)); }
__device__ __forceinline__ HQ ldHQ(const uint2* p) {
    uint2 u = *p; HQ v;
    v.p = *(h2*)&u.x; v.q = *(h2*)&u.y; return v;
}
__device__ __forceinline__ void stHQ(uint2* p, HQ v) {
    uint2 u; u.x = *(unsigned*)&v.p; u.y = *(unsigned*)&v.q; *p = u;
}
__device__ __forceinline__ h2 shup(h2 v) {
    unsigned u = *(unsigned*)&v; u = __shfl_up_sync(FULLM, u, 1); return *(h2*)&u;
}
__device__ __forceinline__ h2 shdn(h2 v) {
    unsigned u = *(unsigned*)&v; u = __shfl_down_sync(FULLM, u, 1); return *(h2*)&u;
}

// One sweep step at row Y, ring slot U (compile-time). fp16 tower.
// Ring invariant after step Y: L[j][U] = level-j row (Y-j); (U+2)%3 = that row-1; (U+1)%3 = row-2.
template <int T, int U, bool INIT, bool WRITE_E, bool TOPB, bool BOTB, bool FUSE>
__device__ __forceinline__ void do_step(
    int Y, HQ (&L)[T + 1][3], HQ& nxt, HQ& snxt, float4& onxt,
    const float4*& inPf, const uint2*& inPh, uint2*& skP, const float4*& otP, uint2*& eoP,
    uint2* __restrict__ ring, float& acc_p, float& acc_s,
    int lane, bool loadok, bool outok, bool ledge, bool redge,
    int b0, int b1)
{
    const h2 INF2  = hc(0x7C00);
    const h2 NINF2 = hc(0xFC00);
    const h2 ZERO2 = hc(0x0000);
    const __half NINFh = __ushort_as_half(0xFC00);
    constexpr int u  = U;
    constexpr int h1 = (U + 2) % 3;
    constexpr int hh2 = (U + 1) % 3;

    // Advance stream pointers to row Y.
    if (INIT) inPf += ROWQ; else inPh += ROWQ;
    skP += ROWQ;
    if (FUSE) otP += ROWQ;
    if (WRITE_E) eoP += ROWQ;

    // Consume prefetched input row Y; prefetch row Y+1.
    L[0][u] = nxt;
    {
        const int yy = Y + 1;
        bool ok = loadok;
        if (TOPB) ok = ok && (yy >= 0);
        if (BOTB) ok = ok && (yy < IMG_H);
        HQ v = mkHQ(INF2, INF2);
        if (ok) {
            if (INIT) {
                float4 f = inPf[ROWQ];
                v.p = __floats2half2_rn(f.x, f.y);
                v.q = __floats2half2_rn(f.z, f.w);
            } else {
                v = ldHQ(inPh + ROWQ);
            }
        }
        nxt = v;
    }
    // Consume prefetched skel row (Y-2); prefetch row Y-1.
    HQ scur = snxt;
    if (!INIT) {
        const int yy = Y - 1;
        HQ sv = mkHQ(ZERO2, ZERO2);
        if (yy >= b0 && yy < b1 && outok) sv = ldHQ(skP - ROWQ);
        snxt = sv;
    }
    // Consume prefetched other row (Y-T-1, fp32); prefetch row Y-T.
    float4 ocur = onxt;
    if (FUSE) {
        const int yy = Y - T;
        float4 ov = make_float4(0.0f, 0.0f, 0.0f, 0.0f);
        if (yy >= b0 && yy < b1 && outok) ov = otP[-T * ROWQ];
        onxt = ov;
    }

    // Erosion levels: level j computes row r = Y - j from level j-1 rows r-1..r+1
#pragma unroll
    for (int j = 1; j <= T; ++j) {
        const int r = Y - j;
        const HQ up = L[j - 1][hh2];
        const HQ ce = L[j - 1][h1];
        const HQ dn = L[j - 1][u];
        const h2 lf = shup(ce.q);   // left neighbor's (c2,c3)
        const h2 rt = shdn(ce.p);   // right neighbor's (c0,c1)
        const h2 mid = __halves2half2(__high2half(ce.p), __low2half(ce.q));  // (c1,c2)
        const h2 lv  = __halves2half2(__high2half(lf),   __low2half(ce.p));  // (cl,c0)
        const h2 rv  = __halves2half2(__high2half(ce.q), __low2half(rt));    // (c3,cr)
        HQ o;
        o.p = __hmin2(__hmin2(__hmin2(up.p, dn.p), ce.p), __hmin2(lv,  mid));
        o.q = __hmin2(__hmin2(__hmin2(up.q, dn.q), ce.q), __hmin2(mid, rv));
        if (TOPB) { if (r < 0)      o = mkHQ(INF2, INF2); }
        if (BOTB) { if (r >= IMG_H) o = mkHQ(INF2, INF2); }
        L[j][u] = o;
        if (WRITE_E && j == T) {
            if (r >= b0 && r < b1 && outok) stHQ(eoP - T * ROWQ, o);   // row Y-T
        }
    }

    // Deltas: delta_k at row y = Y - k - 2
#pragma unroll
    for (int k = 0; k < T; ++k) {
        const int y = Y - k - 2;
        if (y < b0 || y >= b1) continue;

        HQ A = L[k + 1][hh2];
        const HQ B = L[k + 1][h1];
        HQ C = L[k + 1][u];
        if (TOPB) { if (y == 0)         A = mkHQ(NINF2, NINF2); }
        if (BOTB) { if (y == IMG_H - 1) C = mkHQ(NINF2, NINF2); }

        const h2 vmP = __hmax2(__hmax2(A.p, B.p), C.p);
        const h2 vmQ = __hmax2(__hmax2(A.q, B.q), C.q);
        const h2 lf = shup(vmQ);
        const h2 rt = shdn(vmP);
        const h2 mid = __halves2half2(__high2half(vmP), __low2half(vmQ));
        const h2 lv  = __halves2half2(ledge ? NINFh : __high2half(lf), __low2half(vmP));
        const h2 rv  = __halves2half2(__high2half(vmQ), redge ? NINFh : __low2half(rt));
        const h2 opP = __hmax2(vmP, __hmax2(lv,  mid));
        const h2 opQ = __hmax2(vmQ, __hmax2(mid, rv));

        const HQ e = L[k][hh2];
        const h2 dP = __hmax2(__hsub2(e.p, opP), ZERO2);
        const h2 dQ = __hmax2(__hsub2(e.q, opQ), ZERO2);

        uint2* srow = ring + ((y & 7) << 5) + lane;
        HQ s;
        if (k == 0) {
            if (INIT) s = mkHQ(ZERO2, ZERO2);
            else      s = scur;
        } else {
            s = ldHQ(srow);
        }
        // s += relu(d - s*d) = s + max(fma(-s, d, d), 0)
        s.p = __hadd2(s.p, __hmax2(__hfma2(__hneg2(s.p), dP, dP), ZERO2));
        s.q = __hadd2(s.q, __hmax2(__hfma2(__hneg2(s.q), dQ, dQ), ZERO2));

        if (k == T - 1) {
            if (outok) {
                if (FUSE) {
                    const float2 f0 = __half22float2(s.p);
                    const float2 f1 = __half22float2(s.q);
                    acc_p += f0.x * ocur.x + f0.y * ocur.y + f1.x * ocur.z + f1.y * ocur.w;
                    acc_s += f0.x + f0.y + f1.x + f1.y;
                } else {
                    stHQ(skP - (T + 1) * ROWQ, s);        // row Y-T-1
                }
            }
        } else {
            stHQ(srow, s);
        }
    }
}

template <int T, bool INIT, bool WRITE_E, bool TOPB, bool BOTB, bool FUSE>
__device__ __forceinline__ void sweep(
    const float4* in4f, const uint2* in2h, uint2* eout2,
    uint2* skel2, const float4* other4,
    uint2* __restrict__ ring, double* __restrict__ sums, int t_idx,
    int lane, int gq, bool loadok, bool outok, bool ledge, bool redge,
    int b0, int b1)
{
    // NSTEPS >= (b1-b0) + 2T + 4, multiple of 3 (max band = 94 rows)
    constexpr int NST = (T == 6) ? 111 : 108;
    const h2 INF2  = hc(0x7C00);
    const h2 ZERO2 = hc(0x0000);

    HQ L[T + 1][3];
#pragma unroll
    for (int j = 0; j <= T; ++j)
#pragma unroll
        for (int s = 0; s < 3; ++s)
            L[j][s] = mkHQ(INF2, INF2);

    const int Ys = b0 - (T + 3);

    // Stream pointers at "row Ys-1"; first do_step advances them to row Ys.
    const float4* inPf = INIT    ? (in4f   + (Ys - 1) * ROWQ + gq) : nullptr;
    const uint2*  inPh = !INIT   ? (in2h   + (Ys - 1) * ROWQ + gq) : nullptr;
    uint2*        skP  = skel2   + (Ys - 1) * ROWQ + gq;
    const float4* otP  = FUSE    ? (other4 + (Ys - 1) * ROWQ + gq) : nullptr;
    uint2*        eoP  = WRITE_E ? (eout2  + (Ys - 1) * ROWQ + gq) : nullptr;

    HQ nxt = mkHQ(INF2, INF2);
    {
        bool ok = loadok;
        if (TOPB) ok = ok && (Ys >= 0);
        if (ok) {
            if (INIT) {
                float4 f = in4f[Ys * ROWQ + gq];
                nxt.p = __floats2half2_rn(f.x, f.y);
                nxt.q = __floats2half2_rn(f.z, f.w);
            } else {
                nxt = ldHQ(in2h + Ys * ROWQ + gq);
            }
        }
    }
    HQ snxt = mkHQ(ZERO2, ZERO2);
    float4 onxt = make_float4(0.0f, 0.0f, 0.0f, 0.0f);
    float acc_p = 0.0f, acc_s = 0.0f;

    for (int d = 0; d < NST; d += 3) {
        do_step<T, 0, INIT, WRITE_E, TOPB, BOTB, FUSE>(Ys + d,     L, nxt, snxt, onxt,
            inPf, inPh, skP, otP, eoP, ring, acc_p, acc_s,
            lane, loadok, outok, ledge, redge, b0, b1);
        do_step<T, 1, INIT, WRITE_E, TOPB, BOTB, FUSE>(Ys + d + 1, L, nxt, snxt, onxt,
            inPf, inPh, skP, otP, eoP, ring, acc_p, acc_s,
            lane, loadok, outok, ledge, redge, b0, b1);
        do_step<T, 2, INIT, WRITE_E, TOPB, BOTB, FUSE>(Ys + d + 2, L, nxt, snxt, onxt,
            inPf, inPh, skP, otP, eoP, ring, acc_p, acc_s,
            lane, loadok, outok, ledge, redge, b0, b1);
    }

    if (FUSE) {
#pragma unroll
        for (int off = 16; off > 0; off >>= 1) {
            acc_p += __shfl_down_sync(FULLM, acc_p, off);
            acc_s += __shfl_down_sync(FULLM, acc_s, off);
        }
        if (lane == 0) {
            atomicAdd(&sums[2 * t_idx],     (double)acc_p);
            atomicAdd(&sums[2 * t_idx + 1], (double)acc_s);
        }
    }
}

// Warp-autonomous erosion tower: no block barriers. fp16 tower data.
// regs=82 measured at occ 5 -> 6 blocks/SM fits the 85-reg budget (65536/768).
template <int T, bool INIT, bool WRITE_E, bool FUSE>
__global__ __launch_bounds__(128, 6)
void tower(const float* __restrict__ p0, const float* __restrict__ p1,
           const float* __restrict__ o0, const float* __restrict__ o1,
           const __half* __restrict__ hin, __half* __restrict__ eout,
           __half* __restrict__ gskel)
{
    __shared__ uint2 ring[4][8 * 32];

    const int wid  = threadIdx.x >> 5;
    const int lane = threadIdx.x & 31;
    const int w    = blockIdx.x * 4 + wid;
    const int n    = w / (NBANDS * STRIPS);
    const int rem  = w % (NBANDS * STRIPS);
    const int band = rem / STRIPS;
    const int strip = rem % STRIPS;
    const int b0 = band * BROW0;
    const int b1 = (band == NBANDS - 1) ? IMG_H : (b0 + BROW0);

    const int gq = 26 * strip - 3 + lane;
    const bool loadok = (gq >= 0) && (gq < ROWQ);
    const bool outok  = (lane >= 3) && (lane < 29) && (gq < ROWQ);
    const bool ledge  = (gq == 0);
    const bool redge  = (gq == ROWQ - 1);

    const float* srcf = nullptr;
    if (INIT) srcf = (n < N_IMG) ? (p0 + (size_t)n * IMG_PIX)
                                 : (p1 + (size_t)(n - N_IMG) * IMG_PIX);
    const __half* srch = INIT ? nullptr : (hin + (size_t)n * IMG_PIX);
    const float* oth = nullptr;
    const int t_idx = (n >= N_IMG) ? 1 : 0;
    if (FUSE) oth = (n < N_IMG) ? (o0 + (size_t)n * IMG_PIX)
                                : (o1 + (size_t)(n - N_IMG) * IMG_PIX);

    const float4* in4f  = (const float4*)srcf;
    const uint2*  in2h  = (const uint2*)srch;
    uint2*        eout2 = (uint2*)(WRITE_E ? (eout + (size_t)n * IMG_PIX) : nullptr);
    uint2*        skel2 = (uint2*)(gskel + (size_t)n * IMG_PIX);
    const float4* oth4  = (const float4*)oth;
    uint2* myring = &ring[wid][0];

    if (band == 0)
        sweep<T, INIT, WRITE_E, true,  false, FUSE>(in4f, in2h, eout2, skel2, oth4, myring,
            g_sums, t_idx, lane, gq, loadok, outok, ledge, redge, b0, b1);
    else if (band == NBANDS - 1)
        sweep<T, INIT, WRITE_E, false, true,  FUSE>(in4f, in2h, eout2, skel2, oth4, myring,
            g_sums, t_idx, lane, gq, loadok, outok, ledge, redge, b0, b1);
    else
        sweep<T, INIT, WRITE_E, false, false, FUSE>(in4f, in2h, eout2, skel2, oth4, myring,
            g_sums, t_idx, lane, gq, loadok, outok, ledge, redge, b0, b1);
}

__global__ void zero_sums(double* sums) {
    if (threadIdx.x < 4) sums[threadIdx.x] = 0.0;
}

__global__ void finalize_cldice(const double* __restrict__ sums, float* __restrict__ out) {
    const double tprec = (sums[0] + SMOOTH) / (sums[1] + SMOOTH);
    const double tsens = (sums[2] + SMOOTH) / (sums[3] + SMOOTH);
    out[0] = (float)(1.0 - 2.0 * (tprec * tsens) / (tprec + tsens));
}

extern "C" void kernel_launch(void* const* d_in, const int* in_sizes, int n_in,
                              void* d_out, int out_size) {
    const float* target = (const float*)d_in[0];
    const float* inputs = (const float*)d_in[1];
    float* out = (float*)d_out;

    static __half* bufA = nullptr;
    static __half* bufB = nullptr;
    static __half* skel = nullptr;
    static double* sums = nullptr;
    if (!bufA) {
        cudaGetSymbolAddress((void**)&bufA, g_bufA);
        cudaGetSymbolAddress((void**)&bufB, g_bufB);
        cudaGetSymbolAddress((void**)&skel, g_skel);
        cudaGetSymbolAddress((void**)&sums, g_sums);
    }

    // warps: 64 images x 11 bands x 10 strips = 7040 -> 1760 blocks x 4 warps
    // (6 blocks/SM -> 888 slots -> 1.98 waves, 99% packed)
    const int NBLK = (2 * N_IMG * NBANDS * STRIPS) / 4;
    const dim3 block(128);

    zero_sums<<<1, 32>>>(sums);

    // Erosion tower E_0..E_26, deltas 0..25: passes T = 6,5,5,5,5 (fp16).
    // Pass 1 converts fp32->fp16; last pass fuses the skel/other reduction.
    tower<6, true,  true,  false><<<NBLK, block>>>(inputs, target, nullptr, nullptr,
                                                   nullptr, bufA, skel);
    tower<5, false, true,  false><<<NBLK, block>>>(nullptr, nullptr, nullptr, nullptr,
                                                   bufA, bufB, skel);
    tower<5, false, true,  false><<<NBLK, block>>>(nullptr, nullptr, nullptr, nullptr,
                                                   bufB, bufA, skel);
    tower<5, false, true,  false><<<NBLK, block>>>(nullptr, nullptr, nullptr, nullptr,
                                                   bufA, bufB, skel);
    tower<5, false, false, true ><<<NBLK, block>>>(nullptr, nullptr, target, inputs,
                                                   bufB, nullptr, skel);

    finalize_cldice<<<1, 1>>>(sums, out);
}

// round 15
// speedup vs baseline: 2.0709x; 1.0749x over previous
#include <cuda_runtime.h>
#include <cuda_fp16.h>
#include <cstdint>

#define IMG_W   1024
#define IMG_H   1024
#define IMG_PIX (IMG_W * IMG_H)
#define N_IMG   32
#define TOTAL_F ((size_t)N_IMG * IMG_PIX)
#define SMOOTH  1e-5
#define FULLM   0xffffffffu
#define NBANDS  11                    // bands 0..9: 93 rows; band 10: 94 rows
#define BROW0   93
#define STRIPS  10
#define ROWQ    (IMG_W / 4)           // quads (4 cols) per row

typedef __half2 h2;
struct HQ { h2 p, q; };               // 4 columns: p=(c0,c1), q=(c2,c3)

// Scratch (no cudaMalloc allowed): fp16 intermediates
__device__ __half g_bufA[2 * N_IMG * IMG_PIX];
__device__ __half g_bufB[2 * N_IMG * IMG_PIX];
__device__ __half g_skel[2 * N_IMG * IMG_PIX];
__device__ double g_sums[4];

__device__ __forceinline__ HQ mkHQ(h2 a, h2 b) { HQ r; r.p = a; r.q = b; return r; }
__device__ __forceinline__ h2 hc(unsigned short u) { return __half2half2(__ushort_as_half(u)); }
__device__ __forceinline__ HQ ldHQ(const uint2* p) {
    uint2 u = *p; HQ v;
    v.p = *(h2*)&u.x; v.q = *(h2*)&u.y; return v;
}
__device__ __forceinline__ void stHQ(uint2* p, HQ v) {
    uint2 u; u.x = *(unsigned*)&v.p; u.y = *(unsigned*)&v.q; *p = u;
}
__device__ __forceinline__ h2 shup(h2 v) {
    unsigned u = *(unsigned*)&v; u = __shfl_up_sync(FULLM, u, 1); return *(h2*)&u;
}
__device__ __forceinline__ h2 shdn(h2 v) {
    unsigned u = *(unsigned*)&v; u = __shfl_down_sync(FULLM, u, 1); return *(h2*)&u;
}

// One sweep step at row Y, ring slot U (compile-time). fp16 tower.
// Ring invariant after step Y: L[j][U] = level-j row (Y-j); (U+2)%3 = that row-1; (U+1)%3 = row-2.
// All tower values lie in [0,1]; .SAT arithmetic implements the relu's exactly
// on the fma pipe (alu-pipe HMNMX2 offload).
template <int T, int U, bool INIT, bool WRITE_E, bool TOPB, bool BOTB, bool FUSE>
__device__ __forceinline__ void do_step(
    int Y, HQ (&L)[T + 1][3], HQ& nxt, HQ& snxt, float4& onxt,
    const float4*& inPf, const uint2*& inPh, uint2*& skP, const float4*& otP, uint2*& eoP,
    uint2* __restrict__ ring, float& acc_p, float& acc_s,
    int lane, bool loadok, bool outok, bool ledge, bool redge,
    int b0, int b1)
{
    const h2 INF2  = hc(0x7C00);
    const h2 NINF2 = hc(0xFC00);
    const h2 ZERO2 = hc(0x0000);
    const __half NINFh = __ushort_as_half(0xFC00);
    constexpr int u  = U;
    constexpr int h1 = (U + 2) % 3;
    constexpr int hh2 = (U + 1) % 3;

    // Advance stream pointers to row Y.
    if (INIT) inPf += ROWQ; else inPh += ROWQ;
    skP += ROWQ;
    if (FUSE) otP += ROWQ;
    if (WRITE_E) eoP += ROWQ;

    // Consume prefetched input row Y; prefetch row Y+1.
    L[0][u] = nxt;
    {
        const int yy = Y + 1;
        bool ok = loadok;
        if (TOPB) ok = ok && (yy >= 0);
        if (BOTB) ok = ok && (yy < IMG_H);
        HQ v = mkHQ(INF2, INF2);
        if (ok) {
            if (INIT) {
                float4 f = inPf[ROWQ];
                v.p = __floats2half2_rn(f.x, f.y);
                v.q = __floats2half2_rn(f.z, f.w);
            } else {
                v = ldHQ(inPh + ROWQ);
            }
        }
        nxt = v;
    }
    // Consume prefetched skel row (Y-2); prefetch row Y-1.
    HQ scur = snxt;
    if (!INIT) {
        const int yy = Y - 1;
        HQ sv = mkHQ(ZERO2, ZERO2);
        if (yy >= b0 && yy < b1 && outok) sv = ldHQ(skP - ROWQ);
        snxt = sv;
    }
    // Consume prefetched other row (Y-T-1, fp32); prefetch row Y-T.
    float4 ocur = onxt;
    if (FUSE) {
        const int yy = Y - T;
        float4 ov = make_float4(0.0f, 0.0f, 0.0f, 0.0f);
        if (yy >= b0 && yy < b1 && outok) ov = otP[-T * ROWQ];
        onxt = ov;
    }

    // Erosion levels: level j computes row r = Y - j from level j-1 rows r-1..r+1
#pragma unroll
    for (int j = 1; j <= T; ++j) {
        const int r = Y - j;
        const HQ up = L[j - 1][hh2];
        const HQ ce = L[j - 1][h1];
        const HQ dn = L[j - 1][u];
        const h2 lf = shup(ce.q);   // left neighbor's (c2,c3)
        const h2 rt = shdn(ce.p);   // right neighbor's (c0,c1)
        const h2 mid = __halves2half2(__high2half(ce.p), __low2half(ce.q));  // (c1,c2)
        const h2 lv  = __halves2half2(__high2half(lf),   __low2half(ce.p));  // (cl,c0)
        const h2 rv  = __halves2half2(__high2half(ce.q), __low2half(rt));    // (c3,cr)
        HQ o;
        o.p = __hmin2(__hmin2(__hmin2(up.p, dn.p), ce.p), __hmin2(lv,  mid));
        o.q = __hmin2(__hmin2(__hmin2(up.q, dn.q), ce.q), __hmin2(mid, rv));
        if (TOPB) { if (r < 0)      o = mkHQ(INF2, INF2); }
        if (BOTB) { if (r >= IMG_H) o = mkHQ(INF2, INF2); }
        L[j][u] = o;
        if (WRITE_E && j == T) {
            if (r >= b0 && r < b1 && outok) stHQ(eoP - T * ROWQ, o);   // row Y-T
        }
    }

    // Deltas: delta_k at row y = Y - k - 2
#pragma unroll
    for (int k = 0; k < T; ++k) {
        const int y = Y - k - 2;
        if (y < b0 || y >= b1) continue;

        HQ A = L[k + 1][hh2];
        const HQ B = L[k + 1][h1];
        HQ C = L[k + 1][u];
        if (TOPB) { if (y == 0)         A = mkHQ(NINF2, NINF2); }
        if (BOTB) { if (y == IMG_H - 1) C = mkHQ(NINF2, NINF2); }

        const h2 vmP = __hmax2(__hmax2(A.p, B.p), C.p);
        const h2 vmQ = __hmax2(__hmax2(A.q, B.q), C.q);
        const h2 lf = shup(vmQ);
        const h2 rt = shdn(vmP);
        const h2 mid = __halves2half2(__high2half(vmP), __low2half(vmQ));
        const h2 lv  = __halves2half2(ledge ? NINFh : __high2half(lf), __low2half(vmP));
        const h2 rv  = __halves2half2(__high2half(vmQ), redge ? NINFh : __low2half(rt));
        const h2 opP = __hmax2(vmP, __hmax2(lv,  mid));
        const h2 opQ = __hmax2(vmQ, __hmax2(mid, rv));

        // delta = relu(e - op): e,op in [0,1] -> SAT subtract is exact relu (fma pipe)
        const HQ e = L[k][hh2];
        const h2 dP = __hsub2_sat(e.p, opP);
        const h2 dQ = __hsub2_sat(e.q, opQ);

        uint2* srow = ring + ((y & 7) << 5) + lane;
        HQ s;
        if (k == 0) {
            if (INIT) s = mkHQ(ZERO2, ZERO2);
            else      s = scur;
        } else {
            s = ldHQ(srow);
        }
        // s += relu(d - s*d): SAT fma clamps negatives to 0 = exact relu (fma pipe)
        s.p = __hadd2(s.p, __hfma2_sat(__hneg2(s.p), dP, dP));
        s.q = __hadd2(s.q, __hfma2_sat(__hneg2(s.q), dQ, dQ));

        if (k == T - 1) {
            if (outok) {
                if (FUSE) {
                    const float2 f0 = __half22float2(s.p);
                    const float2 f1 = __half22float2(s.q);
                    acc_p += f0.x * ocur.x + f0.y * ocur.y + f1.x * ocur.z + f1.y * ocur.w;
                    acc_s += f0.x + f0.y + f1.x + f1.y;
                } else {
                    stHQ(skP - (T + 1) * ROWQ, s);        // row Y-T-1
                }
            }
        } else {
            stHQ(srow, s);
        }
    }
}

template <int T, bool INIT, bool WRITE_E, bool TOPB, bool BOTB, bool FUSE>
__device__ __forceinline__ void sweep(
    const float4* in4f, const uint2* in2h, uint2* eout2,
    uint2* skel2, const float4* other4,
    uint2* __restrict__ ring, double* __restrict__ sums, int t_idx,
    int lane, int gq, bool loadok, bool outok, bool ledge, bool redge,
    int b0, int b1)
{
    // NSTEPS >= (b1-b0) + 2T + 4, multiple of 3 (max band = 94 rows)
    constexpr int NST = (T == 6) ? 111 : 108;
    const h2 INF2  = hc(0x7C00);
    const h2 ZERO2 = hc(0x0000);

    HQ L[T + 1][3];
#pragma unroll
    for (int j = 0; j <= T; ++j)
#pragma unroll
        for (int s = 0; s < 3; ++s)
            L[j][s] = mkHQ(INF2, INF2);

    const int Ys = b0 - (T + 3);

    // Stream pointers at "row Ys-1"; first do_step advances them to row Ys.
    const float4* inPf = INIT    ? (in4f   + (Ys - 1) * ROWQ + gq) : nullptr;
    const uint2*  inPh = !INIT   ? (in2h   + (Ys - 1) * ROWQ + gq) : nullptr;
    uint2*        skP  = skel2   + (Ys - 1) * ROWQ + gq;
    const float4* otP  = FUSE    ? (other4 + (Ys - 1) * ROWQ + gq) : nullptr;
    uint2*        eoP  = WRITE_E ? (eout2  + (Ys - 1) * ROWQ + gq) : nullptr;

    HQ nxt = mkHQ(INF2, INF2);
    {
        bool ok = loadok;
        if (TOPB) ok = ok && (Ys >= 0);
        if (ok) {
            if (INIT) {
                float4 f = in4f[Ys * ROWQ + gq];
                nxt.p = __floats2half2_rn(f.x, f.y);
                nxt.q = __floats2half2_rn(f.z, f.w);
            } else {
                nxt = ldHQ(in2h + Ys * ROWQ + gq);
            }
        }
    }
    HQ snxt = mkHQ(ZERO2, ZERO2);
    float4 onxt = make_float4(0.0f, 0.0f, 0.0f, 0.0f);
    float acc_p = 0.0f, acc_s = 0.0f;

    for (int d = 0; d < NST; d += 3) {
        do_step<T, 0, INIT, WRITE_E, TOPB, BOTB, FUSE>(Ys + d,     L, nxt, snxt, onxt,
            inPf, inPh, skP, otP, eoP, ring, acc_p, acc_s,
            lane, loadok, outok, ledge, redge, b0, b1);
        do_step<T, 1, INIT, WRITE_E, TOPB, BOTB, FUSE>(Ys + d + 1, L, nxt, snxt, onxt,
            inPf, inPh, skP, otP, eoP, ring, acc_p, acc_s,
            lane, loadok, outok, ledge, redge, b0, b1);
        do_step<T, 2, INIT, WRITE_E, TOPB, BOTB, FUSE>(Ys + d + 2, L, nxt, snxt, onxt,
            inPf, inPh, skP, otP, eoP, ring, acc_p, acc_s,
            lane, loadok, outok, ledge, redge, b0, b1);
    }

    if (FUSE) {
#pragma unroll
        for (int off = 16; off > 0; off >>= 1) {
            acc_p += __shfl_down_sync(FULLM, acc_p, off);
            acc_s += __shfl_down_sync(FULLM, acc_s, off);
        }
        if (lane == 0) {
            atomicAdd(&sums[2 * t_idx],     (double)acc_p);
            atomicAdd(&sums[2 * t_idx + 1], (double)acc_s);
        }
    }
}

// Warp-autonomous erosion tower: no block barriers. fp16 tower data.
template <int T, bool INIT, bool WRITE_E, bool FUSE>
__global__ __launch_bounds__(128, 6)
void tower(const float* __restrict__ p0, const float* __restrict__ p1,
           const float* __restrict__ o0, const float* __restrict__ o1,
           const __half* __restrict__ hin, __half* __restrict__ eout,
           __half* __restrict__ gskel)
{
    __shared__ uint2 ring[4][8 * 32];

    const int wid  = threadIdx.x >> 5;
    const int lane = threadIdx.x & 31;
    const int w    = blockIdx.x * 4 + wid;
    const int n    = w / (NBANDS * STRIPS);
    const int rem  = w % (NBANDS * STRIPS);
    const int band = rem / STRIPS;
    const int strip = rem % STRIPS;
    const int b0 = band * BROW0;
    const int b1 = (band == NBANDS - 1) ? IMG_H : (b0 + BROW0);

    const int gq = 26 * strip - 3 + lane;
    const bool loadok = (gq >= 0) && (gq < ROWQ);
    const bool outok  = (lane >= 3) && (lane < 29) && (gq < ROWQ);
    const bool ledge  = (gq == 0);
    const bool redge  = (gq == ROWQ - 1);

    const float* srcf = nullptr;
    if (INIT) srcf = (n < N_IMG) ? (p0 + (size_t)n * IMG_PIX)
                                 : (p1 + (size_t)(n - N_IMG) * IMG_PIX);
    const __half* srch = INIT ? nullptr : (hin + (size_t)n * IMG_PIX);
    const float* oth = nullptr;
    const int t_idx = (n >= N_IMG) ? 1 : 0;
    if (FUSE) oth = (n < N_IMG) ? (o0 + (size_t)n * IMG_PIX)
                                : (o1 + (size_t)(n - N_IMG) * IMG_PIX);

    const float4* in4f  = (const float4*)srcf;
    const uint2*  in2h  = (const uint2*)srch;
    uint2*        eout2 = (uint2*)(WRITE_E ? (eout + (size_t)n * IMG_PIX) : nullptr);
    uint2*        skel2 = (uint2*)(gskel + (size_t)n * IMG_PIX);
    const float4* oth4  = (const float4*)oth;
    uint2* myring = &ring[wid][0];

    if (band == 0)
        sweep<T, INIT, WRITE_E, true,  false, FUSE>(in4f, in2h, eout2, skel2, oth4, myring,
            g_sums, t_idx, lane, gq, loadok, outok, ledge, redge, b0, b1);
    else if (band == NBANDS - 1)
        sweep<T, INIT, WRITE_E, false, true,  FUSE>(in4f, in2h, eout2, skel2, oth4, myring,
            g_sums, t_idx, lane, gq, loadok, outok, ledge, redge, b0, b1);
    else
        sweep<T, INIT, WRITE_E, false, false, FUSE>(in4f, in2h, eout2, skel2, oth4, myring,
            g_sums, t_idx, lane, gq, loadok, outok, ledge, redge, b0, b1);
}

__global__ void zero_sums(double* sums) {
    if (threadIdx.x < 4) sums[threadIdx.x] = 0.0;
}

__global__ void finalize_cldice(const double* __restrict__ sums, float* __restrict__ out) {
    const double tprec = (sums[0] + SMOOTH) / (sums[1] + SMOOTH);
    const double tsens = (sums[2] + SMOOTH) / (sums[3] + SMOOTH);
    out[0] = (float)(1.0 - 2.0 * (tprec * tsens) / (tprec + tsens));
}

extern "C" void kernel_launch(void* const* d_in, const int* in_sizes, int n_in,
                              void* d_out, int out_size) {
    const float* target = (const float*)d_in[0];
    const float* inputs = (const float*)d_in[1];
    float* out = (float*)d_out;

    static __half* bufA = nullptr;
    static __half* bufB = nullptr;
    static __half* skel = nullptr;
    static double* sums = nullptr;
    if (!bufA) {
        cudaGetSymbolAddress((void**)&bufA, g_bufA);
        cudaGetSymbolAddress((void**)&bufB, g_bufB);
        cudaGetSymbolAddress((void**)&skel, g_skel);
        cudaGetSymbolAddress((void**)&sums, g_sums);
    }

    // warps: 64 images x 11 bands x 10 strips = 7040 -> 1760 blocks x 4 warps
    // (6 blocks/SM -> 888 slots -> 1.98 waves, 99% packed)
    const int NBLK = (2 * N_IMG * NBANDS * STRIPS) / 4;
    const dim3 block(128);

    zero_sums<<<1, 32>>>(sums);

    // Erosion tower E_0..E_26, deltas 0..25: passes T = 6,5,5,5,5 (fp16).
    // Pass 1 converts fp32->fp16; last pass fuses the skel/other reduction.
    tower<6, true,  true,  false><<<NBLK, block>>>(inputs, target, nullptr, nullptr,
                                                   nullptr, bufA, skel);
    tower<5, false, true,  false><<<NBLK, block>>>(nullptr, nullptr, nullptr, nullptr,
                                                   bufA, bufB, skel);
    tower<5, false, true,  false><<<NBLK, block>>>(nullptr, nullptr, nullptr, nullptr,
                                                   bufB, bufA, skel);
    tower<5, false, true,  false><<<NBLK, block>>>(nullptr, nullptr, nullptr, nullptr,
                                                   bufA, bufB, skel);
    tower<5, false, false, true ><<<NBLK, block>>>(nullptr, nullptr, target, inputs,
                                                   bufB, nullptr, skel);

    finalize_cldice<<<1, 1>>>(sums, out);
}